// round 3
// baseline (speedup 1.0000x reference)
#include <cuda_runtime.h>

// AttentionLite on GB300 — round 2 (fix output scramble permutation)
// B=4, G=8, HEADS=4, C=32 per group, H=W=32, K=7, P=3 -> padded 38x38
// m-dimension = G*K*K = 392 (softmax window shared across query groups)
//
// Reference epilogue: transpose(0,4,2,3,1)+reshape scrambles axes:
//   out_final[b, g*32 + h, w, c] = O[b, c, h, w, g]

#define NB   4
#define NG   8
#define NHD  4
#define CW   32          // OUT_W == IN_W
#define HH   32
#define WW   32
#define KS   7
#define PD   3
#define HP   38          // H + 2*P
#define NM   392         // G*K*K
#define MPAD 416         // padded m (104 float4 tiles)
#define MSK  424         // smem stride for K/S rows (16B-aligned, conflict-free fill)
#define MSV  417         // smem stride for V rows (odd -> conflict-free column reads)
#define NPIX (HH*WW)

#define ATTN_SMEM ((32*MSK + 32*MSV + 1024 + 32) * 4)   // = 111872 bytes

// ---------------- scratch (no allocs allowed) ----------------
__device__ float g_q[NB*NPIX*1024];      // [b][p][c][r], r = h*8+g   (16 MB)
__device__ float g_k[NB*HP*HP*256];      // [b][sy][sx][c][g']        (5.9 MB)
__device__ float g_v[NB*HP*HP*256];

// ---------------- q conv: q[b,p,c,h,g] = sum_i x[b,g*32+i,p]*wq[g,h*32+c,i]+bq ----------------
__global__ void __launch_bounds__(256) qconv_kernel(const float* __restrict__ x,
                                                    const float* __restrict__ wq,
                                                    const float* __restrict__ bq) {
    int bp = blockIdx.x;               // b*1024 + p
    int b = bp >> 10, p = bp & 1023;
    __shared__ float xs[256];          // xs[i*8+g] = x[b, g*32+i, p]
    int t = threadIdx.x;
    {
        float v = x[(b*256 + t)*1024 + p];
        xs[(t & 31)*8 + (t >> 5)] = v;
    }
    __syncthreads();
    int g = t & 7, hh = (t >> 3) & 3, c0 = t >> 5;
    float acc[4];
    const float4* w4[4];
    #pragma unroll
    for (int k = 0; k < 4; k++) {
        int c = c0 + 8*k;
        int o = g*128 + hh*32 + c;
        acc[k] = bq[o];
        w4[k] = (const float4*)(wq + o*32);
    }
    #pragma unroll
    for (int i4 = 0; i4 < 8; i4++) {
        float xv0 = xs[(i4*4+0)*8 + g];
        float xv1 = xs[(i4*4+1)*8 + g];
        float xv2 = xs[(i4*4+2)*8 + g];
        float xv3 = xs[(i4*4+3)*8 + g];
        #pragma unroll
        for (int k = 0; k < 4; k++) {
            float4 w = w4[k][i4];
            acc[k] += xv0*w.x + xv1*w.y + xv2*w.z + xv3*w.w;
        }
    }
    #pragma unroll
    for (int k = 0; k < 4; k++) {
        int idx = (c0 + 8*k)*32 + hh*8 + g;     // [c][r]
        g_q[bp*1024 + idx] = acc[k];
    }
}

// ---------------- k/v conv on padded grid (bias at padded locations too) ----------------
__global__ void __launch_bounds__(256) kvconv_kernel(const float* __restrict__ x,
                                                     const float* __restrict__ wk,
                                                     const float* __restrict__ bk,
                                                     const float* __restrict__ wv,
                                                     const float* __restrict__ bv) {
    int bp = blockIdx.x;                       // b*1444 + sy*38 + sx
    int b = bp / (HP*HP);
    int sp = bp - b*(HP*HP);
    int sy = sp / HP, sx = sp - sy*HP;
    int iy = sy - PD, ix = sx - PD;
    bool inb = (iy >= 0) && (iy < HH) && (ix >= 0) && (ix < WW);
    __shared__ float xs[256];                  // xs[i*8+g]
    int t = threadIdx.x;
    {
        float v = inb ? x[(b*256 + t)*1024 + iy*32 + ix] : 0.f;
        xs[(t & 31)*8 + (t >> 5)] = v;
    }
    __syncthreads();
    int c = t >> 3, g = t & 7;
    const float4* wk4 = (const float4*)(wk + (g*32 + c)*32);
    const float4* wv4 = (const float4*)(wv + (g*32 + c)*32);
    float ak = bk[g*32 + c], av = bv[g*32 + c];
    #pragma unroll
    for (int i4 = 0; i4 < 8; i4++) {
        float xv0 = xs[(i4*4+0)*8 + g];
        float xv1 = xs[(i4*4+1)*8 + g];
        float xv2 = xs[(i4*4+2)*8 + g];
        float xv3 = xs[(i4*4+3)*8 + g];
        float4 a = wk4[i4];
        float4 bw = wv4[i4];
        ak += xv0*a.x + xv1*a.y + xv2*a.z + xv3*a.w;
        av += xv0*bw.x + xv1*bw.y + xv2*bw.z + xv3*bw.w;
    }
    g_k[bp*256 + c*8 + g] = ak;                // [c][g'] (g' fastest)
    g_v[bp*256 + c*8 + g] = av;
}

// ---------------- attention: one CTA per (b, pixel) ----------------
__device__ __forceinline__ void s_compute_tile(const float* Ks, const float* qs,
                                               int mtile, int ty, float* a) {
    #pragma unroll
    for (int u = 0; u < 16; u++) a[u] = 0.f;
    int mcol = mtile * 4;
    #pragma unroll
    for (int cc = 0; cc < 32; cc++) {
        float4 kv = *(const float4*)(Ks + cc*MSK + mcol);
        float4 qv = *(const float4*)(qs + cc*32 + 4*ty);
        a[0]  += qv.x*kv.x; a[1]  += qv.x*kv.y; a[2]  += qv.x*kv.z; a[3]  += qv.x*kv.w;
        a[4]  += qv.y*kv.x; a[5]  += qv.y*kv.y; a[6]  += qv.y*kv.z; a[7]  += qv.y*kv.w;
        a[8]  += qv.z*kv.x; a[9]  += qv.z*kv.y; a[10] += qv.z*kv.z; a[11] += qv.z*kv.w;
        a[12] += qv.w*kv.x; a[13] += qv.w*kv.y; a[14] += qv.w*kv.z; a[15] += qv.w*kv.w;
    }
}

__device__ __forceinline__ void s_store_tile(float* Ks, int mtile, int ty, const float* a) {
    int mcol = mtile * 4;
    #pragma unroll
    for (int rr = 0; rr < 4; rr++) {
        float4 v = make_float4(a[rr*4+0], a[rr*4+1], a[rr*4+2], a[rr*4+3]);
        *(float4*)(Ks + (4*ty + rr)*MSK + mcol) = v;
    }
}

__global__ void __launch_bounds__(256, 2) attn_kernel(const float* __restrict__ rel_h,
                                                      const float* __restrict__ rel_w,
                                                      float* __restrict__ out) {
    extern __shared__ float sm[];
    float* Ks   = sm;                       // [32 c][MSK] K(+rel); reused as S [32 r][MSK]
    float* Vs   = sm + 32*MSK;              // [32 c][MSV]
    float* qs   = Vs + 32*MSV;              // [32 c][32 r]
    float* rinv = qs + 1024;                // [32]

    int bp = blockIdx.x;
    int b = bp >> 10, p = bp & 1023;
    int px = p >> 5, py = p & 31;           // px = h (row), py = w (col)
    int t = threadIdx.x;
    int tx = t & 31, ty = t >> 5;

    // stage q (contiguous [c][r] layout)
    ((float4*)qs)[t] = ((const float4*)(g_q + bp*1024))[t];

    // stage K window (+rel) and V window
    {
        int c = t >> 3, gq = t & 7;
        float rh[KS];
        #pragma unroll
        for (int u = 0; u < KS; u++)
            rh[u] = (c < 16) ? rel_h[c*56 + gq*7 + u] : rel_w[(c-16)*56 + gq*7 + u];
        const float* kbase = g_k + ((b*HP + px)*HP + py)*256 + t;
        const float* vbase = g_v + ((b*HP + px)*HP + py)*256 + t;
        for (int i = 0; i < KS; i++) {
            #pragma unroll
            for (int j = 0; j < KS; j++) {
                int m = gq*49 + i*7 + j;
                int off = (i*HP + j)*256;
                float rel = (c < 16) ? rh[i] : rh[j];
                Ks[c*MSK + m] = kbase[off] + rel;
                Vs[c*MSV + m] = vbase[off];
            }
        }
        if (t < 32) {
            for (int m = NM; m < MPAD; m++) Ks[t*MSK + m] = 0.f;
        }
    }
    __syncthreads();

    // S = q^T (32r x 32c) * K (32c x 416m), 4x4 register tiles.
    // Double-buffered so S can overwrite the K smem region column-range by column-range.
    float acc[2][16];
    s_compute_tile(Ks, qs, tx, ty, acc[0]);
    #pragma unroll
    for (int k = 1; k < 4; k++) {
        __syncthreads();
        if (tx + 32*k < 104) s_compute_tile(Ks, qs, tx + 32*k, ty, acc[k & 1]);
        s_store_tile(Ks, tx + 32*(k-1), ty, acc[(k-1) & 1]);
    }
    __syncthreads();
    if (tx + 96 < 104) s_store_tile(Ks, tx + 96, ty, acc[1]);
    __syncthreads();

    // softmax per row r over m in [0, 392); warp ty does rows 4ty..4ty+3
    #pragma unroll
    for (int rr = 0; rr < 4; rr++) {
        int r = ty*4 + rr;
        float* Srow = Ks + r*MSK;
        float mx = -1e30f;
        for (int m = tx; m < NM; m += 32) mx = fmaxf(mx, Srow[m]);
        #pragma unroll
        for (int off = 16; off; off >>= 1) mx = fmaxf(mx, __shfl_xor_sync(0xffffffffu, mx, off));
        float sum = 0.f;
        for (int m = tx; m < NM; m += 32) {
            float e = __expf(Srow[m] - mx);
            Srow[m] = e;
            sum += e;
        }
        #pragma unroll
        for (int off = 16; off; off >>= 1) sum += __shfl_xor_sync(0xffffffffu, sum, off);
        if (tx == 0) rinv[r] = 1.f / sum;
    }
    __syncthreads();

    // head-collapse: Ag[g][m] = sum_h attn[h*8+g][m] (normalized), written in place to rows 0..7
    for (int idx = t; idx < 8*NM; idx += 256) {
        int g = idx / NM;
        int m = idx - g*NM;
        float s = 0.f;
        #pragma unroll
        for (int hh = 0; hh < 4; hh++) {
            int r = hh*8 + g;
            s += Ks[r*MSK + m] * rinv[r];
        }
        Ks[g*MSK + m] = s;
    }
    __syncthreads();

    // O[c][g] = sum_m Ag[g][m] * V[c][m];  thread = (c=tx, g=ty)
    // Reference epilogue scramble: out[b, g*32 + h, w, c] = O[b, c, h, w, g]
    {
        int c = tx, g = ty;
        const float* Ag = Ks + g*MSK;
        const float* Vr = Vs + c*MSV;
        float o = 0.f;
        #pragma unroll 8
        for (int m = 0; m < NM; m++) o += Ag[m] * Vr[m];
        out[b*262144 + (g*32 + px)*1024 + py*32 + c] = o;
    }
}

// ---------------- launch ----------------
extern "C" void kernel_launch(void* const* d_in, const int* in_sizes, int n_in,
                              void* d_out, int out_size) {
    const float* x   = (const float*)d_in[0];
    const float* wq  = (const float*)d_in[1];
    const float* bq  = (const float*)d_in[2];
    const float* wk  = (const float*)d_in[3];
    const float* bk  = (const float*)d_in[4];
    const float* wv  = (const float*)d_in[5];
    const float* bv  = (const float*)d_in[6];
    const float* rlh = (const float*)d_in[7];
    const float* rlw = (const float*)d_in[8];
    float* out = (float*)d_out;

    qconv_kernel<<<NB*NPIX, 256>>>(x, wq, bq);
    kvconv_kernel<<<NB*HP*HP, 256>>>(x, wk, bk, wv, bv);
    cudaFuncSetAttribute(attn_kernel, cudaFuncAttributeMaxDynamicSharedMemorySize, ATTN_SMEM);
    attn_kernel<<<NB*NPIX, 256, ATTN_SMEM>>>(rlh, rlw, out);
}

// round 4
// speedup vs baseline: 1.3688x; 1.3688x over previous
#include <cuda_runtime.h>

#define NB 4
#define NG 8
#define HH 32
#define WW 32
#define KS 7
#define PD 3
#define HP 38
#define NM 392
#define MPAD 448
#define MSK 452     // mod32=4: staging (c,g) banks conflict-free; mult of 4 for f4
#define MSV 393     // odd: O-GEMM column reads conflict-free
#define NPIX 1024

#define SM_KS 0
#define SM_VS (32*MSK)            // 14464
#define SM_QS (SM_VS + 32*MSV)    // 27040
#define SM_MB (SM_QS + 1024)      // 28064  [32r][8w]
#define SM_RI (SM_MB + 256)       // 28320
#define ATTN_SMEM ((SM_RI + 32)*4)   // 113408 B -> 2 CTA/SM

#define QC_WS 0                    // [128 o][33]
#define QC_XS (128*33)             // [32 k][64 p]
#define QC_OS (QC_XS + 32*64)      // [64 p][132]
#define QCONV_SMEM ((QC_OS + 64*132)*4)   // 58880 B

__device__ float g_q[NB*NPIX*1024];   // [b][p][g*128 + hh*32 + c]
__device__ float g_k[NB*HP*HP*256];   // [b][sp][c*8+g]
__device__ float g_v[NB*HP*HP*256];

typedef unsigned long long u64;
__device__ __forceinline__ u64 pk2(float a, float b) {
    u64 r; asm("mov.b64 %0, {%1,%2};" : "=l"(r) : "f"(a), "f"(b)); return r;
}
__device__ __forceinline__ void up2(u64 v, float& a, float& b) {
    asm("mov.b64 {%0,%1}, %2;" : "=f"(a), "=f"(b) : "l"(v));
}
#define FMA2(d,a,b) asm("fma.rn.f32x2 %0, %1, %2, %0;" : "+l"(d) : "l"(a), "l"(b))

// ---------------- q conv: per (b,g) GEMM 128o x 64p, K=32 ----------------
__global__ void __launch_bounds__(256) qconv_kernel(const float* __restrict__ x,
                                                    const float* __restrict__ wq,
                                                    const float* __restrict__ bq) {
    extern __shared__ float sm[];
    float* Ws = sm + QC_WS;  // [o*33 + k]
    float* Xs = sm + QC_XS;  // [k*64 + p]
    float* Os = sm + QC_OS;  // [p*132 + o]
    int pt = blockIdx.x, g = blockIdx.y, b = blockIdx.z;
    int t = threadIdx.x;

    #pragma unroll
    for (int u = 0; u < 16; u++) {
        int e = t + 256*u;
        Ws[(e >> 5)*33 + (e & 31)] = wq[g*4096 + e];
    }
    #pragma unroll
    for (int u = 0; u < 8; u++) {
        int e = t + 256*u;
        int k = e >> 6, p = e & 63;
        Xs[e] = x[((b*NG + g)*32 + k)*1024 + pt*64 + p];
    }
    __syncthreads();

    int to = t >> 4, tp = t & 15;
    int o0 = to*8, p0 = tp*4;
    u64 a[8][2];
    #pragma unroll
    for (int i = 0; i < 8; i++) {
        float bi = bq[g*128 + o0 + i];
        a[i][0] = pk2(bi, bi); a[i][1] = a[i][0];
    }
    #pragma unroll 4
    for (int k = 0; k < 32; k++) {
        ulonglong2 xv = *(const ulonglong2*)(Xs + k*64 + p0);
        #pragma unroll
        for (int i = 0; i < 8; i++) {
            float w = Ws[(o0 + i)*33 + k];
            u64 w2 = pk2(w, w);
            FMA2(a[i][0], w2, xv.x);
            FMA2(a[i][1], w2, xv.y);
        }
    }
    #pragma unroll
    for (int i = 0; i < 8; i++)
        #pragma unroll
        for (int j = 0; j < 2; j++) {
            float lo, hi; up2(a[i][j], lo, hi);
            Os[(p0 + 2*j    )*132 + o0 + i] = lo;
            Os[(p0 + 2*j + 1)*132 + o0 + i] = hi;
        }
    __syncthreads();
    #pragma unroll
    for (int u = 0; u < 8; u++) {
        int e = t + 256*u;        // 2048 float4
        int p = e >> 5, o4 = e & 31;
        float4 v = *(const float4*)(Os + p*132 + o4*4);
        *(float4*)(g_q + (long)((b*1024 + pt*64 + p))*1024 + g*128 + o4*4) = v;
    }
}

// ---------------- k/v conv (unchanged; coalesced [c*8+g] writes) ----------------
__global__ void __launch_bounds__(256) kvconv_kernel(const float* __restrict__ x,
                                                     const float* __restrict__ wk,
                                                     const float* __restrict__ bk,
                                                     const float* __restrict__ wv,
                                                     const float* __restrict__ bv) {
    int bp = blockIdx.x;
    int b = bp / (HP*HP);
    int sp = bp - b*(HP*HP);
    int sy = sp / HP, sx = sp - sy*HP;
    int iy = sy - PD, ix = sx - PD;
    bool inb = (iy >= 0) && (iy < HH) && (ix >= 0) && (ix < WW);
    __shared__ float xs[256];
    int t = threadIdx.x;
    {
        float v = inb ? x[(b*256 + t)*1024 + iy*32 + ix] : 0.f;
        xs[(t & 31)*8 + (t >> 5)] = v;
    }
    __syncthreads();
    int c = t >> 3, g = t & 7;
    const float4* wk4 = (const float4*)(wk + (g*32 + c)*32);
    const float4* wv4 = (const float4*)(wv + (g*32 + c)*32);
    float ak = bk[g*32 + c], av = bv[g*32 + c];
    #pragma unroll
    for (int i4 = 0; i4 < 8; i4++) {
        float x0 = xs[(i4*4+0)*8 + g];
        float x1 = xs[(i4*4+1)*8 + g];
        float x2 = xs[(i4*4+2)*8 + g];
        float x3 = xs[(i4*4+3)*8 + g];
        float4 a = wk4[i4];
        float4 bw = wv4[i4];
        ak += x0*a.x + x1*a.y + x2*a.z + x3*a.w;
        av += x0*bw.x + x1*bw.y + x2*bw.z + x3*bw.w;
    }
    g_k[bp*256 + c*8 + g] = ak;
    g_v[bp*256 + c*8 + g] = av;
}

// ---------------- attention ----------------
__device__ __forceinline__ void sgemm_warp(float* Ks, const float* qs, float* mb,
                                           int w, int tx) {
    int r0 = (tx & 3)*8;
    int m0 = w*64 + (tx >> 2)*8;
    u64 acc[8][4];
    #pragma unroll
    for (int i = 0; i < 8; i++)
        #pragma unroll
        for (int j = 0; j < 4; j++) acc[i][j] = 0ull;
    #pragma unroll 4
    for (int cc = 0; cc < 32; cc++) {
        const float* kr = Ks + cc*MSK + m0;
        ulonglong2 ka = *(const ulonglong2*)kr;
        ulonglong2 kb = *(const ulonglong2*)(kr + 4);
        float4 qa = *(const float4*)(qs + cc*32 + r0);
        float4 qb = *(const float4*)(qs + cc*32 + r0 + 4);
        float qv[8] = {qa.x, qa.y, qa.z, qa.w, qb.x, qb.y, qb.z, qb.w};
        #pragma unroll
        for (int i = 0; i < 8; i++) {
            u64 q2 = pk2(qv[i], qv[i]);
            FMA2(acc[i][0], q2, ka.x);
            FMA2(acc[i][1], q2, ka.y);
            FMA2(acc[i][2], q2, kb.x);
            FMA2(acc[i][3], q2, kb.y);
        }
    }
    #pragma unroll
    for (int i = 0; i < 8; i++) {
        float lo, hi, mx = -1e30f;
        #pragma unroll
        for (int j = 0; j < 4; j++) { up2(acc[i][j], lo, hi); mx = fmaxf(mx, fmaxf(lo, hi)); }
        mx = fmaxf(mx, __shfl_xor_sync(0xffffffffu, mx, 4));
        mx = fmaxf(mx, __shfl_xor_sync(0xffffffffu, mx, 8));
        mx = fmaxf(mx, __shfl_xor_sync(0xffffffffu, mx, 16));
        if ((tx >> 2) == 0) mb[(r0 + i)*8 + w] = mx;
        *(ulonglong2*)(Ks + (r0 + i)*MSK + m0)     = make_ulonglong2(acc[i][0], acc[i][1]);
        *(ulonglong2*)(Ks + (r0 + i)*MSK + m0 + 4) = make_ulonglong2(acc[i][2], acc[i][3]);
    }
}

__global__ void __launch_bounds__(256, 2) attn_kernel(const float* __restrict__ rel_h,
                                                      const float* __restrict__ rel_w,
                                                      float* __restrict__ out) {
    extern __shared__ float sm[];
    float* Ks   = sm + SM_KS;
    float* Vs   = sm + SM_VS;
    float* qs   = sm + SM_QS;
    float* mb   = sm + SM_MB;
    float* rinv = sm + SM_RI;

    int bp = blockIdx.x;
    int b = bp >> 10, p = bp & 1023;
    int px = p >> 5, py = p & 31;
    int t = threadIdx.x;
    int tx = t & 31, ty = t >> 5;

    // stage q: qs[c*32 + hh*8 + g] = g_q[bp*1024 + g*128 + hh*32 + c]
    {
        float4 qv = ((const float4*)(g_q + (long)bp*1024))[t];
        int s = t*4;
        int g = s >> 7, hh = (s >> 5) & 3, c0 = s & 31;
        qs[(c0+0)*32 + hh*8 + g] = qv.x;
        qs[(c0+1)*32 + hh*8 + g] = qv.y;
        qs[(c0+2)*32 + hh*8 + g] = qv.z;
        qs[(c0+3)*32 + hh*8 + g] = qv.w;
    }

    // stage K(+rel), V
    {
        int c = t >> 3, gq = t & 7;
        float rh[KS];
        #pragma unroll
        for (int u = 0; u < KS; u++)
            rh[u] = (c < 16) ? rel_h[c*56 + gq*7 + u] : rel_w[(c - 16)*56 + gq*7 + u];
        const float* kbase = g_k + ((long)(b*HP + px)*HP + py)*256 + t;
        const float* vbase = g_v + ((long)(b*HP + px)*HP + py)*256 + t;
        for (int i = 0; i < KS; i++) {
            #pragma unroll
            for (int j = 0; j < KS; j++) {
                int m = gq*49 + i*7 + j;
                int off = (i*HP + j)*256;
                float rel = (c < 16) ? rh[i] : rh[j];
                Ks[c*MSK + m] = kbase[off] + rel;
                Vs[c*MSV + m] = vbase[off];
            }
        }
        if (t < 32) {
            #pragma unroll
            for (int m = NM; m < MPAD; m++) Ks[t*MSK + m] = 0.f;
        }
    }
    __syncthreads();

    // S = q^T K ; warps 0..6 own disjoint 64-col ranges; in-place store; reg max
    if (ty < 7) sgemm_warp(Ks, qs, mb, ty, tx);
    __syncthreads();

    // softmax rows 4ty..4ty+3 over m<392
    #pragma unroll
    for (int rr = 0; rr < 4; rr++) {
        int r = ty*4 + rr;
        float* Srow = Ks + r*MSK;
        float mx = (tx < 7) ? mb[r*8 + tx] : -1e30f;
        #pragma unroll
        for (int off = 16; off; off >>= 1) mx = fmaxf(mx, __shfl_xor_sync(0xffffffffu, mx, off));
        float sum = 0.f;
        for (int m = tx; m < NM; m += 32) {
            float e = __expf(Srow[m] - mx);
            Srow[m] = e;
            sum += e;
        }
        #pragma unroll
        for (int off = 16; off; off >>= 1) sum += __shfl_xor_sync(0xffffffffu, sum, off);
        if (tx == 0) rinv[r] = 1.f / sum;
    }
    __syncthreads();

    // collapse heads: Ag[g][m] = sum_h attn[h*8+g][m]*rinv, in place rows 0..7
    for (int idx = t; idx < 8*NM; idx += 256) {
        int g = idx / NM;
        int m = idx - g*NM;
        float s = 0.f;
        #pragma unroll
        for (int hh = 0; hh < 4; hh++) {
            int r = hh*8 + g;
            s += Ks[r*MSK + m] * rinv[r];
        }
        Ks[g*MSK + m] = s;
    }
    __syncthreads();

    // O[c][g] = sum_m Ag[g][m]*V[c][m]; out[b, g*32+px, py, c]
    {
        int c = tx, g = ty;
        const float* Ag = Ks + g*MSK;
        const float* Vr = Vs + c*MSV;
        float o = 0.f;
        #pragma unroll 8
        for (int m = 0; m < NM; m++) o += Ag[m] * Vr[m];
        out[b*262144 + (g*32 + px)*1024 + py*32 + c] = o;
    }
}

// ---------------- launch ----------------
extern "C" void kernel_launch(void* const* d_in, const int* in_sizes, int n_in,
                              void* d_out, int out_size) {
    const float* x   = (const float*)d_in[0];
    const float* wq  = (const float*)d_in[1];
    const float* bq  = (const float*)d_in[2];
    const float* wk  = (const float*)d_in[3];
    const float* bk  = (const float*)d_in[4];
    const float* wv  = (const float*)d_in[5];
    const float* bv  = (const float*)d_in[6];
    const float* rlh = (const float*)d_in[7];
    const float* rlw = (const float*)d_in[8];
    float* out = (float*)d_out;

    cudaFuncSetAttribute(qconv_kernel, cudaFuncAttributeMaxDynamicSharedMemorySize, QCONV_SMEM);
    cudaFuncSetAttribute(attn_kernel, cudaFuncAttributeMaxDynamicSharedMemorySize, ATTN_SMEM);

    qconv_kernel<<<dim3(16, 8, 4), 256, QCONV_SMEM>>>(x, wq, bq);
    kvconv_kernel<<<NB*HP*HP, 256>>>(x, wk, bk, wv, bv);
    attn_kernel<<<NB*NPIX, 256, ATTN_SMEM>>>(rlh, rlw, out);
}

// round 5
// speedup vs baseline: 1.3707x; 1.0013x over previous
#include <cuda_runtime.h>

#define NB 4
#define NG 8
#define HH 32
#define WW 32
#define KS 7
#define PD 3
#define HP 38
#define NM 392
#define MPAD 448
#define MSK 452     // mod32=4: staging (c,g) banks conflict-free; mult of 4 for f4
#define MSV 393     // odd: O-GEMM column reads conflict-free
#define NPIX 1024

#define SM_KS 0
#define SM_VS (32*MSK)            // 14464
#define SM_QS (SM_VS + 32*MSV)    // 27040
#define SM_MB (SM_QS + 1024)      // 28064  [32r][8w]
#define SM_RI (SM_MB + 256)       // 28320
#define ATTN_SMEM ((SM_RI + 32)*4)   // 113408 B -> 2 CTA/SM

#define QC_WS 0                    // [128 o][33]
#define QC_XS (128*33)             // [32 k][64 p]
#define QC_OS (QC_XS + 32*64)      // [64 p][132]
#define QCONV_SMEM ((QC_OS + 64*132)*4)   // 58880 B

__device__ float g_q[NB*NPIX*1024];   // [b][p][g*128 + hh*32 + c]
__device__ float g_k[NB*HP*HP*256];   // [b][sp][c*8+g]
__device__ float g_v[NB*HP*HP*256];

typedef unsigned long long u64;
__device__ __forceinline__ u64 pk2(float a, float b) {
    u64 r; asm("mov.b64 %0, {%1,%2};" : "=l"(r) : "f"(a), "f"(b)); return r;
}
__device__ __forceinline__ void up2(u64 v, float& a, float& b) {
    asm("mov.b64 {%0,%1}, %2;" : "=f"(a), "=f"(b) : "l"(v));
}
#define FMA2(d,a,b) asm("fma.rn.f32x2 %0, %1, %2, %0;" : "+l"(d) : "l"(a), "l"(b))

// ---------------- q conv: per (b,g) GEMM 128o x 64p, K=32 ----------------
__global__ void __launch_bounds__(256) qconv_kernel(const float* __restrict__ x,
                                                    const float* __restrict__ wq,
                                                    const float* __restrict__ bq) {
    extern __shared__ float sm[];
    float* Ws = sm + QC_WS;  // [o*33 + k]
    float* Xs = sm + QC_XS;  // [k*64 + p]
    float* Os = sm + QC_OS;  // [p*132 + o]
    int pt = blockIdx.x, g = blockIdx.y, b = blockIdx.z;
    int t = threadIdx.x;

    #pragma unroll
    for (int u = 0; u < 16; u++) {
        int e = t + 256*u;
        Ws[(e >> 5)*33 + (e & 31)] = wq[g*4096 + e];
    }
    #pragma unroll
    for (int u = 0; u < 8; u++) {
        int e = t + 256*u;
        int k = e >> 6, p = e & 63;
        Xs[e] = x[((b*NG + g)*32 + k)*1024 + pt*64 + p];
    }
    __syncthreads();

    int to = t >> 4, tp = t & 15;
    int o0 = to*8, p0 = tp*4;
    u64 a[8][2];
    #pragma unroll
    for (int i = 0; i < 8; i++) {
        float bi = bq[g*128 + o0 + i];
        a[i][0] = pk2(bi, bi); a[i][1] = a[i][0];
    }
    #pragma unroll 4
    for (int k = 0; k < 32; k++) {
        ulonglong2 xv = *(const ulonglong2*)(Xs + k*64 + p0);
        #pragma unroll
        for (int i = 0; i < 8; i++) {
            float w = Ws[(o0 + i)*33 + k];
            u64 w2 = pk2(w, w);
            FMA2(a[i][0], w2, xv.x);
            FMA2(a[i][1], w2, xv.y);
        }
    }
    #pragma unroll
    for (int i = 0; i < 8; i++)
        #pragma unroll
        for (int j = 0; j < 2; j++) {
            float lo, hi; up2(a[i][j], lo, hi);
            Os[(p0 + 2*j    )*132 + o0 + i] = lo;
            Os[(p0 + 2*j + 1)*132 + o0 + i] = hi;
        }
    __syncthreads();
    #pragma unroll
    for (int u = 0; u < 8; u++) {
        int e = t + 256*u;        // 2048 float4
        int p = e >> 5, o4 = e & 31;
        float4 v = *(const float4*)(Os + p*132 + o4*4);
        *(float4*)(g_q + (long)((b*1024 + pt*64 + p))*1024 + g*128 + o4*4) = v;
    }
}

// ---------------- k/v conv (unchanged; coalesced [c*8+g] writes) ----------------
__global__ void __launch_bounds__(256) kvconv_kernel(const float* __restrict__ x,
                                                     const float* __restrict__ wk,
                                                     const float* __restrict__ bk,
                                                     const float* __restrict__ wv,
                                                     const float* __restrict__ bv) {
    int bp = blockIdx.x;
    int b = bp / (HP*HP);
    int sp = bp - b*(HP*HP);
    int sy = sp / HP, sx = sp - sy*HP;
    int iy = sy - PD, ix = sx - PD;
    bool inb = (iy >= 0) && (iy < HH) && (ix >= 0) && (ix < WW);
    __shared__ float xs[256];
    int t = threadIdx.x;
    {
        float v = inb ? x[(b*256 + t)*1024 + iy*32 + ix] : 0.f;
        xs[(t & 31)*8 + (t >> 5)] = v;
    }
    __syncthreads();
    int c = t >> 3, g = t & 7;
    const float4* wk4 = (const float4*)(wk + (g*32 + c)*32);
    const float4* wv4 = (const float4*)(wv + (g*32 + c)*32);
    float ak = bk[g*32 + c], av = bv[g*32 + c];
    #pragma unroll
    for (int i4 = 0; i4 < 8; i4++) {
        float x0 = xs[(i4*4+0)*8 + g];
        float x1 = xs[(i4*4+1)*8 + g];
        float x2 = xs[(i4*4+2)*8 + g];
        float x3 = xs[(i4*4+3)*8 + g];
        float4 a = wk4[i4];
        float4 bw = wv4[i4];
        ak += x0*a.x + x1*a.y + x2*a.z + x3*a.w;
        av += x0*bw.x + x1*bw.y + x2*bw.z + x3*bw.w;
    }
    g_k[bp*256 + c*8 + g] = ak;
    g_v[bp*256 + c*8 + g] = av;
}

// ---------------- attention ----------------
__device__ __forceinline__ void sgemm_warp(float* Ks, const float* qs, float* mb,
                                           int w, int tx) {
    int r0 = (tx & 3)*8;
    int m0 = w*64 + (tx >> 2)*8;
    u64 acc[8][4];
    #pragma unroll
    for (int i = 0; i < 8; i++)
        #pragma unroll
        for (int j = 0; j < 4; j++) acc[i][j] = 0ull;
    #pragma unroll 4
    for (int cc = 0; cc < 32; cc++) {
        const float* kr = Ks + cc*MSK + m0;
        ulonglong2 ka = *(const ulonglong2*)kr;
        ulonglong2 kb = *(const ulonglong2*)(kr + 4);
        float4 qa = *(const float4*)(qs + cc*32 + r0);
        float4 qb = *(const float4*)(qs + cc*32 + r0 + 4);
        float qv[8] = {qa.x, qa.y, qa.z, qa.w, qb.x, qb.y, qb.z, qb.w};
        #pragma unroll
        for (int i = 0; i < 8; i++) {
            u64 q2 = pk2(qv[i], qv[i]);
            FMA2(acc[i][0], q2, ka.x);
            FMA2(acc[i][1], q2, ka.y);
            FMA2(acc[i][2], q2, kb.x);
            FMA2(acc[i][3], q2, kb.y);
        }
    }
    #pragma unroll
    for (int i = 0; i < 8; i++) {
        float lo, hi, mx = -1e30f;
        #pragma unroll
        for (int j = 0; j < 4; j++) { up2(acc[i][j], lo, hi); mx = fmaxf(mx, fmaxf(lo, hi)); }
        mx = fmaxf(mx, __shfl_xor_sync(0xffffffffu, mx, 4));
        mx = fmaxf(mx, __shfl_xor_sync(0xffffffffu, mx, 8));
        mx = fmaxf(mx, __shfl_xor_sync(0xffffffffu, mx, 16));
        if ((tx >> 2) == 0) mb[(r0 + i)*8 + w] = mx;
        *(ulonglong2*)(Ks + (r0 + i)*MSK + m0)     = make_ulonglong2(acc[i][0], acc[i][1]);
        *(ulonglong2*)(Ks + (r0 + i)*MSK + m0 + 4) = make_ulonglong2(acc[i][2], acc[i][3]);
    }
}

__global__ void __launch_bounds__(256, 2) attn_kernel(const float* __restrict__ rel_h,
                                                      const float* __restrict__ rel_w,
                                                      float* __restrict__ out) {
    extern __shared__ float sm[];
    float* Ks   = sm + SM_KS;
    float* Vs   = sm + SM_VS;
    float* qs   = sm + SM_QS;
    float* mb   = sm + SM_MB;
    float* rinv = sm + SM_RI;

    int bp = blockIdx.x;
    int b = bp >> 10, p = bp & 1023;
    int px = p >> 5, py = p & 31;
    int t = threadIdx.x;
    int tx = t & 31, ty = t >> 5;

    // stage q: qs[c*32 + hh*8 + g] = g_q[bp*1024 + g*128 + hh*32 + c]
    {
        float4 qv = ((const float4*)(g_q + (long)bp*1024))[t];
        int s = t*4;
        int g = s >> 7, hh = (s >> 5) & 3, c0 = s & 31;
        qs[(c0+0)*32 + hh*8 + g] = qv.x;
        qs[(c0+1)*32 + hh*8 + g] = qv.y;
        qs[(c0+2)*32 + hh*8 + g] = qv.z;
        qs[(c0+3)*32 + hh*8 + g] = qv.w;
    }

    // stage K(+rel), V
    {
        int c = t >> 3, gq = t & 7;
        float rh[KS];
        #pragma unroll
        for (int u = 0; u < KS; u++)
            rh[u] = (c < 16) ? rel_h[c*56 + gq*7 + u] : rel_w[(c - 16)*56 + gq*7 + u];
        const float* kbase = g_k + ((long)(b*HP + px)*HP + py)*256 + t;
        const float* vbase = g_v + ((long)(b*HP + px)*HP + py)*256 + t;
        for (int i = 0; i < KS; i++) {
            #pragma unroll
            for (int j = 0; j < KS; j++) {
                int m = gq*49 + i*7 + j;
                int off = (i*HP + j)*256;
                float rel = (c < 16) ? rh[i] : rh[j];
                Ks[c*MSK + m] = kbase[off] + rel;
                Vs[c*MSV + m] = vbase[off];
            }
        }
        if (t < 32) {
            #pragma unroll
            for (int m = NM; m < MPAD; m++) Ks[t*MSK + m] = 0.f;
        }
    }
    __syncthreads();

    // S = q^T K ; warps 0..6 own disjoint 64-col ranges; in-place store; reg max
    if (ty < 7) sgemm_warp(Ks, qs, mb, ty, tx);
    __syncthreads();

    // softmax rows 4ty..4ty+3 over m<392
    #pragma unroll
    for (int rr = 0; rr < 4; rr++) {
        int r = ty*4 + rr;
        float* Srow = Ks + r*MSK;
        float mx = (tx < 7) ? mb[r*8 + tx] : -1e30f;
        #pragma unroll
        for (int off = 16; off; off >>= 1) mx = fmaxf(mx, __shfl_xor_sync(0xffffffffu, mx, off));
        float sum = 0.f;
        for (int m = tx; m < NM; m += 32) {
            float e = __expf(Srow[m] - mx);
            Srow[m] = e;
            sum += e;
        }
        #pragma unroll
        for (int off = 16; off; off >>= 1) sum += __shfl_xor_sync(0xffffffffu, sum, off);
        if (tx == 0) rinv[r] = 1.f / sum;
    }
    __syncthreads();

    // collapse heads: Ag[g][m] = sum_h attn[h*8+g][m]*rinv, in place rows 0..7
    for (int idx = t; idx < 8*NM; idx += 256) {
        int g = idx / NM;
        int m = idx - g*NM;
        float s = 0.f;
        #pragma unroll
        for (int hh = 0; hh < 4; hh++) {
            int r = hh*8 + g;
            s += Ks[r*MSK + m] * rinv[r];
        }
        Ks[g*MSK + m] = s;
    }
    __syncthreads();

    // O[c][g] = sum_m Ag[g][m]*V[c][m]; out[b, g*32+px, py, c]
    {
        int c = tx, g = ty;
        const float* Ag = Ks + g*MSK;
        const float* Vr = Vs + c*MSV;
        float o = 0.f;
        #pragma unroll 8
        for (int m = 0; m < NM; m++) o += Ag[m] * Vr[m];
        out[b*262144 + (g*32 + px)*1024 + py*32 + c] = o;
    }
}

// ---------------- launch ----------------
extern "C" void kernel_launch(void* const* d_in, const int* in_sizes, int n_in,
                              void* d_out, int out_size) {
    const float* x   = (const float*)d_in[0];
    const float* wq  = (const float*)d_in[1];
    const float* bq  = (const float*)d_in[2];
    const float* wk  = (const float*)d_in[3];
    const float* bk  = (const float*)d_in[4];
    const float* wv  = (const float*)d_in[5];
    const float* bv  = (const float*)d_in[6];
    const float* rlh = (const float*)d_in[7];
    const float* rlw = (const float*)d_in[8];
    float* out = (float*)d_out;

    cudaFuncSetAttribute(qconv_kernel, cudaFuncAttributeMaxDynamicSharedMemorySize, QCONV_SMEM);
    cudaFuncSetAttribute(attn_kernel, cudaFuncAttributeMaxDynamicSharedMemorySize, ATTN_SMEM);

    qconv_kernel<<<dim3(16, 8, 4), 256, QCONV_SMEM>>>(x, wq, bq);
    kvconv_kernel<<<NB*HP*HP, 256>>>(x, wk, bk, wv, bv);
    attn_kernel<<<NB*NPIX, 256, ATTN_SMEM>>>(rlh, rlw, out);
}

// round 6
// speedup vs baseline: 1.9804x; 1.4449x over previous
#include <cuda_runtime.h>

#define NB 4
#define NG 8
#define HH 32
#define WW 32
#define KS 7
#define PD 3
#define HP 38
#define NPP 1444      // HP*HP
#define NM 392
#define MPAD 448
#define MSK 452       // mult4, mod32=4
#define MSV 396       // mult4, mod32=12 -> conflict-free f4 column reads
#define NPIX 1024

#define SM_KS 0
#define SM_VS (32*MSK)            // 14464
#define SM_QS (SM_VS + 32*MSV)    // 27136
#define SM_MB (SM_QS + 1024)      // 28160  [32r][8w]
#define SM_RI (SM_MB + 256)       // 28416
#define ATTN_SMEM ((SM_RI + 32)*4)   // 113792 B -> 2 CTA/SM

// conv kernel smem (qconv view)
#define QC_WS 0                    // [128 o][33]
#define QC_XS (128*33)             // [32 k][64 p]
#define QC_OS (QC_XS + 32*64)      // [64 p][132]
#define CONV_SMEM ((QC_OS + 64*132)*4)   // 58880 B
// kv view
#define KV_WS 0                    // [64 o][33]
#define KV_XS (64*33)              // [32 k][128 p]
#define KV_BS (KV_XS + 32*128)     // [64]

__device__ float g_q[NB*NPIX*1024];   // [b][p][g*128 + hh*32 + c]  (q * log2e)
__device__ float g_k[NB*NPP*256];     // [b][sp][c*8+g]
__device__ float g_v[NB*NPP*256];

typedef unsigned long long u64;
__device__ __forceinline__ u64 pk2(float a, float b) {
    u64 r; asm("mov.b64 %0, {%1,%2};" : "=l"(r) : "f"(a), "f"(b)); return r;
}
__device__ __forceinline__ void up2(u64 v, float& a, float& b) {
    asm("mov.b64 {%0,%1}, %2;" : "=f"(a), "=f"(b) : "l"(v));
}
#define FMA2(d,a,b) asm("fma.rn.f32x2 %0, %1, %2, %0;" : "+l"(d) : "l"(a), "l"(b))
__device__ __forceinline__ float ex2(float x) {
    float r; asm("ex2.approx.f32 %0, %1;" : "=f"(r) : "f"(x)); return r;
}

// ================= fused conv kernel =================
// blockIdx.x < 16 : qconv tile (64 px); else kv tile (128 px of padded grid)
__global__ void __launch_bounds__(256) conv_kernel(const float* __restrict__ x,
                                                   const float* __restrict__ wq,
                                                   const float* __restrict__ bq,
                                                   const float* __restrict__ wk,
                                                   const float* __restrict__ bk,
                                                   const float* __restrict__ wv,
                                                   const float* __restrict__ bv) {
    extern __shared__ float sm[];
    int g = blockIdx.y, b = blockIdx.z;
    int t = threadIdx.x;

    if (blockIdx.x < 16) {
        // ---- qconv: per (b,g) GEMM 128o x 64p, K=32; q scaled by log2e ----
        float* Ws = sm + QC_WS;
        float* Xs = sm + QC_XS;
        float* Os = sm + QC_OS;
        int pt = blockIdx.x;
        #pragma unroll
        for (int u = 0; u < 16; u++) {
            int e = t + 256*u;
            Ws[(e >> 5)*33 + (e & 31)] = wq[g*4096 + e];
        }
        #pragma unroll
        for (int u = 0; u < 8; u++) {
            int e = t + 256*u;
            int k = e >> 6, p = e & 63;
            Xs[e] = x[((b*NG + g)*32 + k)*1024 + pt*64 + p];
        }
        __syncthreads();

        int to = t >> 4, tp = t & 15;
        int o0 = to*8, p0 = tp*4;
        u64 a[8][2];
        #pragma unroll
        for (int i = 0; i < 8; i++) {
            float bi = bq[g*128 + o0 + i];
            a[i][0] = pk2(bi, bi); a[i][1] = a[i][0];
        }
        #pragma unroll 4
        for (int k = 0; k < 32; k++) {
            ulonglong2 xv = *(const ulonglong2*)(Xs + k*64 + p0);
            #pragma unroll
            for (int i = 0; i < 8; i++) {
                float w = Ws[(o0 + i)*33 + k];
                u64 w2 = pk2(w, w);
                FMA2(a[i][0], w2, xv.x);
                FMA2(a[i][1], w2, xv.y);
            }
        }
        const float L2E = 1.4426950408889634f;
        #pragma unroll
        for (int i = 0; i < 8; i++)
            #pragma unroll
            for (int j = 0; j < 2; j++) {
                float lo, hi; up2(a[i][j], lo, hi);
                Os[(p0 + 2*j    )*132 + o0 + i] = lo * L2E;
                Os[(p0 + 2*j + 1)*132 + o0 + i] = hi * L2E;
            }
        __syncthreads();
        #pragma unroll
        for (int u = 0; u < 8; u++) {
            int e = t + 256*u;
            int p = e >> 5, o4 = e & 31;
            float4 v = *(const float4*)(Os + p*132 + o4*4);
            *(float4*)(g_q + (long)(b*1024 + pt*64 + p)*1024 + g*128 + o4*4) = v;
        }
    } else {
        // ---- kv conv: per (b,g) GEMM 64o x 128p on padded grid ----
        float* Ws = sm + KV_WS;   // [o*33+k], o<32:K else V
        float* Xs = sm + KV_XS;   // [k*128+p]
        float* bs = sm + KV_BS;
        int pt = blockIdx.x - 16;
        #pragma unroll
        for (int u = 0; u < 8; u++) {
            int e = t + 256*u;
            int o = e >> 5, k = e & 31;
            Ws[o*33 + k] = (o < 32) ? wk[g*1024 + o*32 + k] : wv[g*1024 + (o-32)*32 + k];
        }
        if (t < 64) bs[t] = (t < 32) ? bk[g*32 + t] : bv[g*32 + t - 32];
        #pragma unroll
        for (int u = 0; u < 16; u++) {
            int e = t + 256*u;
            int k = e >> 7, p = e & 127;
            int sp = pt*128 + p;
            float v = 0.f;
            if (sp < NPP) {
                int sy = sp / HP, sx = sp - sy*HP;
                int iy = sy - PD, ix = sx - PD;
                if (iy >= 0 && iy < HH && ix >= 0 && ix < WW)
                    v = x[((b*NG + g)*32 + k)*1024 + iy*32 + ix];
            }
            Xs[k*128 + p] = v;
        }
        __syncthreads();

        int to = t >> 4, tp = t & 15;
        int o0 = to*4, p0 = tp*8;
        u64 acc[4][4];
        #pragma unroll
        for (int oi = 0; oi < 4; oi++) {
            float bi = bs[o0 + oi];
            u64 b2 = pk2(bi, bi);
            #pragma unroll
            for (int pp = 0; pp < 4; pp++) acc[oi][pp] = b2;
        }
        #pragma unroll 4
        for (int k = 0; k < 32; k++) {
            ulonglong2 xa = *(const ulonglong2*)(Xs + k*128 + p0);
            ulonglong2 xb = *(const ulonglong2*)(Xs + k*128 + p0 + 4);
            u64 xx[4] = {xa.x, xa.y, xb.x, xb.y};
            float4 w4 = *(const float4*)(Ws + (o0)*33 + k); // not contiguous; load scalar
            // scalar weights (o-major layout): fix by 4 scalar loads
            float wv4[4] = {Ws[(o0+0)*33 + k], Ws[(o0+1)*33 + k],
                            Ws[(o0+2)*33 + k], Ws[(o0+3)*33 + k]};
            (void)w4;
            #pragma unroll
            for (int oi = 0; oi < 4; oi++) {
                u64 w2 = pk2(wv4[oi], wv4[oi]);
                #pragma unroll
                for (int pp = 0; pp < 4; pp++) FMA2(acc[oi][pp], w2, xx[pp]);
            }
        }
        #pragma unroll
        for (int pp = 0; pp < 4; pp++)
            #pragma unroll
            for (int hf = 0; hf < 2; hf++) {
                int sp = pt*128 + p0 + pp*2 + hf;
                if (sp < NPP) {
                    long base = (long)(b*NPP + sp)*256 + g;
                    #pragma unroll
                    for (int oi = 0; oi < 4; oi++) {
                        int o = o0 + oi;
                        float lo, hi; up2(acc[oi][pp], lo, hi);
                        float val = hf ? hi : lo;
                        if (o < 32) g_k[base + o*8] = val;
                        else        g_v[base + (o-32)*8] = val;
                    }
                }
            }
    }
}

// ================= attention =================
__device__ __forceinline__ void sgemm_warp(float* Ks, const float* qs, float* mb,
                                           int w, int tx) {
    int r0 = (tx & 3)*8;
    int m0 = w*64 + (tx >> 2)*8;
    bool valid = (m0 < NM);          // pad cols align exactly to lane boundaries
    u64 acc[8][4];
    #pragma unroll
    for (int i = 0; i < 8; i++)
        #pragma unroll
        for (int j = 0; j < 4; j++) acc[i][j] = 0ull;
    #pragma unroll 4
    for (int cc = 0; cc < 32; cc++) {
        const float* kr = Ks + cc*MSK + m0;
        ulonglong2 ka = *(const ulonglong2*)kr;
        ulonglong2 kb = *(const ulonglong2*)(kr + 4);
        float4 qa = *(const float4*)(qs + cc*32 + r0);
        float4 qb = *(const float4*)(qs + cc*32 + r0 + 4);
        float qv[8] = {qa.x, qa.y, qa.z, qa.w, qb.x, qb.y, qb.z, qb.w};
        #pragma unroll
        for (int i = 0; i < 8; i++) {
            u64 q2 = pk2(qv[i], qv[i]);
            FMA2(acc[i][0], q2, ka.x);
            FMA2(acc[i][1], q2, ka.y);
            FMA2(acc[i][2], q2, kb.x);
            FMA2(acc[i][3], q2, kb.y);
        }
    }
    // epilogue: exp (base-2, log2e pre-folded into q) + row partial sums
    #pragma unroll
    for (int i = 0; i < 8; i++) {
        float rsum = 0.f;
        #pragma unroll
        for (int j = 0; j < 4; j++) {
            float lo, hi; up2(acc[i][j], lo, hi);
            float e0 = ex2(lo), e1 = ex2(hi);
            rsum += e0 + e1;
            acc[i][j] = pk2(e0, e1);
        }
        if (!valid) rsum = 0.f;
        rsum += __shfl_xor_sync(0xffffffffu, rsum, 4);
        rsum += __shfl_xor_sync(0xffffffffu, rsum, 8);
        rsum += __shfl_xor_sync(0xffffffffu, rsum, 16);
        if ((tx >> 2) == 0) mb[(r0 + i)*8 + w] = rsum;
        *(ulonglong2*)(Ks + (r0 + i)*MSK + m0)     = make_ulonglong2(acc[i][0], acc[i][1]);
        *(ulonglong2*)(Ks + (r0 + i)*MSK + m0 + 4) = make_ulonglong2(acc[i][2], acc[i][3]);
    }
}

__global__ void __launch_bounds__(256, 2) attn_kernel(const float* __restrict__ rel_h,
                                                      const float* __restrict__ rel_w,
                                                      float* __restrict__ out) {
    extern __shared__ float sm[];
    float* Ks   = sm + SM_KS;
    float* Vs   = sm + SM_VS;
    float* qs   = sm + SM_QS;
    float* mb   = sm + SM_MB;
    float* rinv = sm + SM_RI;

    int bp = blockIdx.x;
    int b = bp >> 10, p = bp & 1023;
    int px = p >> 5, py = p & 31;
    int t = threadIdx.x;
    int tx = t & 31, ty = t >> 5;

    // stage q: qs[c*32 + hh*8 + g]
    {
        float4 qv = ((const float4*)(g_q + (long)bp*1024))[t];
        int s = t*4;
        int g = s >> 7, hh = (s >> 5) & 3, c0 = s & 31;
        qs[(c0+0)*32 + hh*8 + g] = qv.x;
        qs[(c0+1)*32 + hh*8 + g] = qv.y;
        qs[(c0+2)*32 + hh*8 + g] = qv.z;
        qs[(c0+3)*32 + hh*8 + g] = qv.w;
    }

    // stage K(+rel), V
    {
        int c = t >> 3, gq = t & 7;
        float rh[KS];
        #pragma unroll
        for (int u = 0; u < KS; u++)
            rh[u] = (c < 16) ? rel_h[c*56 + gq*7 + u] : rel_w[(c - 16)*56 + gq*7 + u];
        const float* kbase = g_k + ((long)(b*HP + px)*HP + py)*256 + t;
        const float* vbase = g_v + ((long)(b*HP + px)*HP + py)*256 + t;
        for (int i = 0; i < KS; i++) {
            #pragma unroll
            for (int j = 0; j < KS; j++) {
                int m = gq*49 + i*7 + j;
                int off = (i*HP + j)*256;
                float rel = (c < 16) ? rh[i] : rh[j];
                Ks[c*MSK + m] = kbase[off] + rel;
                Vs[c*MSV + m] = vbase[off];
            }
        }
        if (t < 32) {
            #pragma unroll
            for (int m = NM; m < MPAD; m++) Ks[t*MSK + m] = 0.f;
        }
    }
    __syncthreads();

    // S = q^T K with fused exp + row partial sums; in-place store
    if (ty < 7) sgemm_warp(Ks, qs, mb, ty, tx);
    __syncthreads();

    if (t < 32) {
        float s = 0.f;
        #pragma unroll
        for (int w = 0; w < 7; w++) s += mb[t*8 + w];
        rinv[t] = 1.f / s;
    }
    __syncthreads();

    // collapse heads (float4): Ag[g][m4] = sum_h E[h*8+g][m4]*rinv[h*8+g]
    {
        float ri[4];
        for (int idx = t; idx < 8*98; idx += 256) {
            int g = idx / 98;
            int m4 = (idx - g*98)*4;
            #pragma unroll
            for (int hh = 0; hh < 4; hh++) ri[hh] = rinv[hh*8 + g];
            float4 a0 = *(const float4*)(Ks + (0*8 + g)*MSK + m4);
            float4 a1 = *(const float4*)(Ks + (1*8 + g)*MSK + m4);
            float4 a2 = *(const float4*)(Ks + (2*8 + g)*MSK + m4);
            float4 a3 = *(const float4*)(Ks + (3*8 + g)*MSK + m4);
            float4 r;
            r.x = a0.x*ri[0] + a1.x*ri[1] + a2.x*ri[2] + a3.x*ri[3];
            r.y = a0.y*ri[0] + a1.y*ri[1] + a2.y*ri[2] + a3.y*ri[3];
            r.z = a0.z*ri[0] + a1.z*ri[1] + a2.z*ri[2] + a3.z*ri[3];
            r.w = a0.w*ri[0] + a1.w*ri[1] + a2.w*ri[2] + a3.w*ri[3];
            *(float4*)(Ks + g*MSK + m4) = r;
        }
    }
    __syncthreads();

    // O[c][g] = sum_m Ag[g][m]*V[c][m]; float4 + f32x2
    {
        int c = tx, g = ty;
        const ulonglong2* Ag = (const ulonglong2*)(Ks + g*MSK);
        const ulonglong2* Vr = (const ulonglong2*)(Vs + c*MSV);
        u64 oacc = 0ull;
        #pragma unroll 7
        for (int mq = 0; mq < 98; mq++) {
            ulonglong2 a = Ag[mq];
            ulonglong2 v = Vr[mq];
            FMA2(oacc, a.x, v.x);
            FMA2(oacc, a.y, v.y);
        }
        float lo, hi; up2(oacc, lo, hi);
        out[b*262144 + (g*32 + px)*1024 + py*32 + c] = lo + hi;
    }
}

// ---------------- launch ----------------
extern "C" void kernel_launch(void* const* d_in, const int* in_sizes, int n_in,
                              void* d_out, int out_size) {
    const float* x   = (const float*)d_in[0];
    const float* wq  = (const float*)d_in[1];
    const float* bq  = (const float*)d_in[2];
    const float* wk  = (const float*)d_in[3];
    const float* bk  = (const float*)d_in[4];
    const float* wv  = (const float*)d_in[5];
    const float* bv  = (const float*)d_in[6];
    const float* rlh = (const float*)d_in[7];
    const float* rlw = (const float*)d_in[8];
    float* out = (float*)d_out;

    cudaFuncSetAttribute(conv_kernel, cudaFuncAttributeMaxDynamicSharedMemorySize, CONV_SMEM);
    cudaFuncSetAttribute(attn_kernel, cudaFuncAttributeMaxDynamicSharedMemorySize, ATTN_SMEM);

    conv_kernel<<<dim3(28, 8, 4), 256, CONV_SMEM>>>(x, wq, bq, wk, bk, wv, bv);
    attn_kernel<<<NB*NPIX, 256, ATTN_SMEM>>>(rlh, rlw, out);
}

// round 8
// speedup vs baseline: 2.2798x; 1.1511x over previous
#include <cuda_runtime.h>

#define NB 4
#define NG 8
#define HH 32
#define WW 32
#define KS 7
#define PD 3
#define HP 38
#define NPP 1444      // HP*HP
#define NM 392
#define VPAD 416      // padded cols consumed by collapse/O-GEMM (104 f4 chunks)
#define MSK 424       // mod32=8: K-staging STS conflict-free; mult of 4
#define MSV 420       // mod32=4: V f4 column reads conflict-free; mult of 4
#define NPIX 1024

#define SM_KS 0
#define SM_VS (32*MSK)            // 13568
#define SM_QS (SM_VS + 32*MSV)    // 27008
#define SM_MB (SM_QS + 1024)      // 28032  [8w][32r]
#define SM_RI (SM_MB + 256)       // 28288
#define ATTN_SMEM ((SM_RI + 32)*4)   // 113280 B -> 2 CTA/SM

// conv kernel smem (qconv view)
#define QC_WS 0                    // [128 o][33]
#define QC_XS (128*33)             // [32 k][64 p]
#define QC_OS (QC_XS + 32*64)      // [64 p][132]
#define CONV_SMEM ((QC_OS + 64*132)*4)   // 58880 B
// kv view
#define KV_WS 0                    // [64 o][33]
#define KV_XS (64*33)              // [32 k][128 p]
#define KV_BS (KV_XS + 32*128)     // [64]

__device__ float g_q[NB*NPIX*1024];   // [b][p][g*128 + hh*32 + c]  (q * log2e)
__device__ float g_k[NB*NPP*256];     // [b][sp][c*8+g]
__device__ float g_v[NB*NPP*256];

typedef unsigned long long u64;
__device__ __forceinline__ u64 pk2(float a, float b) {
    u64 r; asm("mov.b64 %0, {%1,%2};" : "=l"(r) : "f"(a), "f"(b)); return r;
}
__device__ __forceinline__ void up2(u64 v, float& a, float& b) {
    asm("mov.b64 {%0,%1}, %2;" : "=f"(a), "=f"(b) : "l"(v));
}
#define FMA2(d,a,b) asm("fma.rn.f32x2 %0, %1, %2, %0;" : "+l"(d) : "l"(a), "l"(b))
__device__ __forceinline__ float ex2(float x) {
    float r; asm("ex2.approx.f32 %0, %1;" : "=f"(r) : "f"(x)); return r;
}

// ================= fused conv kernel =================
__global__ void __launch_bounds__(256) conv_kernel(const float* __restrict__ x,
                                                   const float* __restrict__ wq,
                                                   const float* __restrict__ bq,
                                                   const float* __restrict__ wk,
                                                   const float* __restrict__ bk,
                                                   const float* __restrict__ wv,
                                                   const float* __restrict__ bv) {
    extern __shared__ float sm[];
    int g = blockIdx.y, b = blockIdx.z;
    int t = threadIdx.x;

    if (blockIdx.x < 16) {
        // ---- qconv: per (b,g) GEMM 128o x 64p, K=32; q scaled by log2e ----
        float* Ws = sm + QC_WS;
        float* Xs = sm + QC_XS;
        float* Os = sm + QC_OS;
        int pt = blockIdx.x;
        #pragma unroll
        for (int u = 0; u < 16; u++) {
            int e = t + 256*u;
            Ws[(e >> 5)*33 + (e & 31)] = wq[g*4096 + e];
        }
        #pragma unroll
        for (int u = 0; u < 8; u++) {
            int e = t + 256*u;
            int k = e >> 6, p = e & 63;
            Xs[e] = x[((b*NG + g)*32 + k)*1024 + pt*64 + p];
        }
        __syncthreads();

        int to = t >> 4, tp = t & 15;
        int o0 = to*8, p0 = tp*4;
        u64 a[8][2];
        #pragma unroll
        for (int i = 0; i < 8; i++) {
            float bi = bq[g*128 + o0 + i];
            a[i][0] = pk2(bi, bi); a[i][1] = a[i][0];
        }
        #pragma unroll 4
        for (int k = 0; k < 32; k++) {
            ulonglong2 xv = *(const ulonglong2*)(Xs + k*64 + p0);
            #pragma unroll
            for (int i = 0; i < 8; i++) {
                float w = Ws[(o0 + i)*33 + k];
                u64 w2 = pk2(w, w);
                FMA2(a[i][0], w2, xv.x);
                FMA2(a[i][1], w2, xv.y);
            }
        }
        const float L2E = 1.4426950408889634f;
        #pragma unroll
        for (int i = 0; i < 8; i++)
            #pragma unroll
            for (int j = 0; j < 2; j++) {
                float lo, hi; up2(a[i][j], lo, hi);
                Os[(p0 + 2*j    )*132 + o0 + i] = lo * L2E;
                Os[(p0 + 2*j + 1)*132 + o0 + i] = hi * L2E;
            }
        __syncthreads();
        #pragma unroll
        for (int u = 0; u < 8; u++) {
            int e = t + 256*u;
            int p = e >> 5, o4 = e & 31;
            float4 v = *(const float4*)(Os + p*132 + o4*4);
            *(float4*)(g_q + (long)(b*1024 + pt*64 + p)*1024 + g*128 + o4*4) = v;
        }
    } else {
        // ---- kv conv: per (b,g) GEMM 64o x 128p on padded grid ----
        float* Ws = sm + KV_WS;
        float* Xs = sm + KV_XS;
        float* bs = sm + KV_BS;
        int pt = blockIdx.x - 16;
        #pragma unroll
        for (int u = 0; u < 8; u++) {
            int e = t + 256*u;
            int o = e >> 5, k = e & 31;
            Ws[o*33 + k] = (o < 32) ? wk[g*1024 + o*32 + k] : wv[g*1024 + (o-32)*32 + k];
        }
        if (t < 64) bs[t] = (t < 32) ? bk[g*32 + t] : bv[g*32 + t - 32];
        #pragma unroll
        for (int u = 0; u < 16; u++) {
            int e = t + 256*u;
            int k = e >> 7, p = e & 127;
            int sp = pt*128 + p;
            float v = 0.f;
            if (sp < NPP) {
                int sy = sp / HP, sx = sp - sy*HP;
                int iy = sy - PD, ix = sx - PD;
                if (iy >= 0 && iy < HH && ix >= 0 && ix < WW)
                    v = x[((b*NG + g)*32 + k)*1024 + iy*32 + ix];
            }
            Xs[k*128 + p] = v;
        }
        __syncthreads();

        int to = t >> 4, tp = t & 15;
        int o0 = to*4, p0 = tp*8;
        u64 acc[4][4];
        #pragma unroll
        for (int oi = 0; oi < 4; oi++) {
            float bi = bs[o0 + oi];
            u64 b2 = pk2(bi, bi);
            #pragma unroll
            for (int pp = 0; pp < 4; pp++) acc[oi][pp] = b2;
        }
        #pragma unroll 4
        for (int k = 0; k < 32; k++) {
            ulonglong2 xa = *(const ulonglong2*)(Xs + k*128 + p0);
            ulonglong2 xb = *(const ulonglong2*)(Xs + k*128 + p0 + 4);
            u64 xx[4] = {xa.x, xa.y, xb.x, xb.y};
            float wv4[4] = {Ws[(o0+0)*33 + k], Ws[(o0+1)*33 + k],
                            Ws[(o0+2)*33 + k], Ws[(o0+3)*33 + k]};
            #pragma unroll
            for (int oi = 0; oi < 4; oi++) {
                u64 w2 = pk2(wv4[oi], wv4[oi]);
                #pragma unroll
                for (int pp = 0; pp < 4; pp++) FMA2(acc[oi][pp], w2, xx[pp]);
            }
        }
        #pragma unroll
        for (int pp = 0; pp < 4; pp++)
            #pragma unroll
            for (int hf = 0; hf < 2; hf++) {
                int sp = pt*128 + p0 + pp*2 + hf;
                if (sp < NPP) {
                    long base = (long)(b*NPP + sp)*256 + g;
                    #pragma unroll
                    for (int oi = 0; oi < 4; oi++) {
                        int o = o0 + oi;
                        float lo, hi; up2(acc[oi][pp], lo, hi);
                        float val = hf ? hi : lo;
                        if (o < 32) g_k[base + o*8] = val;
                        else        g_v[base + (o-32)*8] = val;
                    }
                }
            }
    }
}

// ================= attention =================
__device__ __forceinline__ void sgemm_warp(float* Ks, const float* qs, float* mb,
                                           int w, int tx) {
    int r0 = (tx & 3)*8;
    int m0 = w*64 + (tx >> 2)*8;
    bool valid  = (m0 < NM);      // real columns (exp sums count)
    bool active = (m0 < VPAD);    // columns that must be stored (real + zero pad)
    int ml = active ? m0 : 0;     // safe load address for inactive lanes
    u64 acc[8][4];
    #pragma unroll
    for (int i = 0; i < 8; i++)
        #pragma unroll
        for (int j = 0; j < 4; j++) acc[i][j] = 0ull;
    #pragma unroll 4
    for (int cc = 0; cc < 32; cc++) {
        const float* kr = Ks + cc*MSK + ml;
        ulonglong2 ka = *(const ulonglong2*)kr;
        ulonglong2 kb = *(const ulonglong2*)(kr + 4);
        float4 qa = *(const float4*)(qs + cc*32 + r0);
        float4 qb = *(const float4*)(qs + cc*32 + r0 + 4);
        float qv[8] = {qa.x, qa.y, qa.z, qa.w, qb.x, qb.y, qb.z, qb.w};
        #pragma unroll
        for (int i = 0; i < 8; i++) {
            u64 q2 = pk2(qv[i], qv[i]);
            FMA2(acc[i][0], q2, ka.x);
            FMA2(acc[i][1], q2, ka.y);
            FMA2(acc[i][2], q2, kb.x);
            FMA2(acc[i][3], q2, kb.y);
        }
    }
    // epilogue: exp (base-2; log2e folded into q) + row partial sums; zero pads
    #pragma unroll
    for (int i = 0; i < 8; i++) {
        float rsum = 0.f;
        #pragma unroll
        for (int j = 0; j < 4; j++) {
            float lo, hi; up2(acc[i][j], lo, hi);
            float e0 = ex2(lo), e1 = ex2(hi);
            rsum += e0 + e1;
            acc[i][j] = valid ? pk2(e0, e1) : 0ull;
        }
        if (!valid) rsum = 0.f;
        rsum += __shfl_xor_sync(0xffffffffu, rsum, 4);
        rsum += __shfl_xor_sync(0xffffffffu, rsum, 8);
        rsum += __shfl_xor_sync(0xffffffffu, rsum, 16);
        if ((tx >> 2) == 0) mb[w*32 + r0 + i] = rsum;
        if (active) {   // stores stay within the 424-float row (max 408+8=416)
            *(ulonglong2*)(Ks + (r0 + i)*MSK + m0)     = make_ulonglong2(acc[i][0], acc[i][1]);
            *(ulonglong2*)(Ks + (r0 + i)*MSK + m0 + 4) = make_ulonglong2(acc[i][2], acc[i][3]);
        }
    }
}

__global__ void __launch_bounds__(256, 2) attn_kernel(const float* __restrict__ rel_h,
                                                      const float* __restrict__ rel_w,
                                                      float* __restrict__ out) {
    extern __shared__ float sm[];
    float* Ks   = sm + SM_KS;
    float* Vs   = sm + SM_VS;
    float* qs   = sm + SM_QS;
    float* mb   = sm + SM_MB;    // [8 w][32 r]
    float* rinv = sm + SM_RI;
    float* Rs   = Ks + 8*MSK;    // O-GEMM partials, reuses dead S rows 8..13

    int bp = blockIdx.x;
    int b = bp >> 10, p = bp & 1023;
    int px = p >> 5, py = p & 31;
    int t = threadIdx.x;
    int tx = t & 31, ty = t >> 5;

    // stage q: qs[c*32 + hh*8 + g]
    {
        float4 qv = ((const float4*)(g_q + (long)bp*1024))[t];
        int s = t*4;
        int g = s >> 7, hh = (s >> 5) & 3, c0 = s & 31;
        qs[(c0+0)*32 + hh*8 + g] = qv.x;
        qs[(c0+1)*32 + hh*8 + g] = qv.y;
        qs[(c0+2)*32 + hh*8 + g] = qv.z;
        qs[(c0+3)*32 + hh*8 + g] = qv.w;
    }

    // stage K(+rel), V ; K STS conflict-free (MSK%32==8)
    {
        int c = t >> 3, gq = t & 7;
        float rh[KS];
        #pragma unroll
        for (int u = 0; u < KS; u++)
            rh[u] = (c < 16) ? rel_h[c*56 + gq*7 + u] : rel_w[(c - 16)*56 + gq*7 + u];
        const float* kbase = g_k + ((long)(b*HP + px)*HP + py)*256 + t;
        const float* vbase = g_v + ((long)(b*HP + px)*HP + py)*256 + t;
        for (int i = 0; i < KS; i++) {
            #pragma unroll
            for (int j = 0; j < KS; j++) {
                int m = gq*49 + i*7 + j;
                int off = (i*HP + j)*256;
                float rel = (c < 16) ? rh[i] : rh[j];
                Ks[c*MSK + m] = kbase[off] + rel;
                Vs[c*MSV + m] = vbase[off];
            }
        }
        if (t < 32) {
            #pragma unroll
            for (int m = NM; m < VPAD; m++) Vs[t*MSV + m] = 0.f;
        }
    }
    __syncthreads();

    // S = q^T K with fused exp + row partial sums; pad cols 392..415 stored 0
    if (ty < 7) sgemm_warp(Ks, qs, mb, ty, tx);
    __syncthreads();

    if (t < 32) {
        float s = 0.f;
        #pragma unroll
        for (int w = 0; w < 7; w++) s += mb[w*32 + t];
        rinv[t] = 1.f / s;
    }
    __syncthreads();

    // collapse heads over padded range (pads are 0): Ag[g][0..415]
    for (int idx = t; idx < 8*104; idx += 256) {
        int g = idx / 104;
        int m4 = (idx - g*104)*4;
        float r0 = rinv[g], r1 = rinv[8 + g], r2 = rinv[16 + g], r3 = rinv[24 + g];
        float4 a0 = *(const float4*)(Ks + g*MSK + m4);
        float4 a1 = *(const float4*)(Ks + (8 + g)*MSK + m4);
        float4 a2 = *(const float4*)(Ks + (16 + g)*MSK + m4);
        float4 a3 = *(const float4*)(Ks + (24 + g)*MSK + m4);
        float4 r;
        r.x = a0.x*r0 + a1.x*r1 + a2.x*r2 + a3.x*r3;
        r.y = a0.y*r0 + a1.y*r1 + a2.y*r2 + a3.y*r3;
        r.z = a0.z*r0 + a1.z*r1 + a2.z*r2 + a3.z*r3;
        r.w = a0.w*r0 + a1.w*r1 + a2.w*r2 + a3.w*r3;
        *(float4*)(Ks + g*MSK + m4) = r;
    }
    __syncthreads();

    // O-GEMM split-m: warp w handles 13 f4 chunks; thread c=tx does all 8 g
    {
        u64 og[8];
        #pragma unroll
        for (int g = 0; g < 8; g++) og[g] = 0ull;
        int c = tx, w = ty;
        #pragma unroll
        for (int i = 0; i < 13; i++) {
            int mq = w*13 + i;
            ulonglong2 v = *(const ulonglong2*)(Vs + c*MSV + mq*4);
            #pragma unroll
            for (int g = 0; g < 8; g++) {
                ulonglong2 a = *(const ulonglong2*)(Ks + g*MSK + mq*4);
                FMA2(og[g], a.x, v.x);
                FMA2(og[g], a.y, v.y);
            }
        }
        #pragma unroll
        for (int g = 0; g < 8; g++) {
            float lo, hi; up2(og[g], lo, hi);
            Rs[w*264 + g*33 + c] = lo + hi;
        }
    }
    __syncthreads();

    // final reduce over 8 warps + scrambled store: out[b, g*32+px, py, c]
    {
        int c = tx, g = ty;
        float s = 0.f;
        #pragma unroll
        for (int w = 0; w < 8; w++) s += Rs[w*264 + g*33 + c];
        out[b*262144 + (g*32 + px)*1024 + py*32 + c] = s;
    }
}

// ---------------- launch ----------------
extern "C" void kernel_launch(void* const* d_in, const int* in_sizes, int n_in,
                              void* d_out, int out_size) {
    const float* x   = (const float*)d_in[0];
    const float* wq  = (const float*)d_in[1];
    const float* bq  = (const float*)d_in[2];
    const float* wk  = (const float*)d_in[3];
    const float* bk  = (const float*)d_in[4];
    const float* wv  = (const float*)d_in[5];
    const float* bv  = (const float*)d_in[6];
    const float* rlh = (const float*)d_in[7];
    const float* rlw = (const float*)d_in[8];
    float* out = (float*)d_out;

    cudaFuncSetAttribute(conv_kernel, cudaFuncAttributeMaxDynamicSharedMemorySize, CONV_SMEM);
    cudaFuncSetAttribute(attn_kernel, cudaFuncAttributeMaxDynamicSharedMemorySize, ATTN_SMEM);

    conv_kernel<<<dim3(28, 8, 4), 256, CONV_SMEM>>>(x, wq, bq, wk, bk, wv, bv);
    attn_kernel<<<NB*NPIX, 256, ATTN_SMEM>>>(rlh, rlw, out);
}

// round 9
// speedup vs baseline: 2.4011x; 1.0532x over previous
#include <cuda_runtime.h>

#define NB 4
#define NG 8
#define HH 32
#define WW 32
#define KS 7
#define PD 3
#define HP 38
#define NPP 1444      // HP*HP
#define NM 392
#define VPAD 416      // padded cols consumed by collapse/O-GEMM (104 f4 chunks)
#define MSK 424       // mod32=8: K-staging STS conflict-free; mult of 4
#define MSVT 33       // V transposed row stride [m][c]
#define NPIX 1024

#define SM_KS 0
#define SM_VS (32*MSK)            // 13568
#define SM_QS (SM_VS + VPAD*MSVT) // 13568+13728 = 27296
#define SM_MB (SM_QS + 1024)      // 28320  [8w][32r]
#define SM_RI (SM_MB + 256)       // 28576
#define ATTN_SMEM ((SM_RI + 32)*4)   // 114432 B -> 2 CTA/SM (228KB)

// conv kernel smem (qconv view)
#define QC_WS 0                    // [128 o][33]
#define QC_XS (128*33)             // [32 k][64 p]
#define QC_OS (QC_XS + 32*64)      // [64 p][132]
#define CONV_SMEM ((QC_OS + 64*132)*4)   // 58880 B
// kv view
#define KV_WS 0                    // [64 o][33]
#define KV_XS (64*33)              // [32 k][128 p]
#define KV_BS (KV_XS + 32*128)     // [64]

__device__ float g_q[NB*NPIX*1024];   // [b][p][g*128 + hh*32 + c]  (q * log2e)
__device__ float g_k[NB*NPP*256];     // [b][sp][c*8+g]
__device__ float g_v[NB*NPP*256];

typedef unsigned long long u64;
__device__ __forceinline__ u64 pk2(float a, float b) {
    u64 r; asm("mov.b64 %0, {%1,%2};" : "=l"(r) : "f"(a), "f"(b)); return r;
}
__device__ __forceinline__ void up2(u64 v, float& a, float& b) {
    asm("mov.b64 {%0,%1}, %2;" : "=f"(a), "=f"(b) : "l"(v));
}
#define FMA2(d,a,b) asm("fma.rn.f32x2 %0, %1, %2, %0;" : "+l"(d) : "l"(a), "l"(b))
__device__ __forceinline__ float ex2(float x) {
    float r; asm("ex2.approx.f32 %0, %1;" : "=f"(r) : "f"(x)); return r;
}

// ================= fused conv kernel =================
__global__ void __launch_bounds__(256) conv_kernel(const float* __restrict__ x,
                                                   const float* __restrict__ wq,
                                                   const float* __restrict__ bq,
                                                   const float* __restrict__ wk,
                                                   const float* __restrict__ bk,
                                                   const float* __restrict__ wv,
                                                   const float* __restrict__ bv) {
    extern __shared__ float sm[];
    int g = blockIdx.y, b = blockIdx.z;
    int t = threadIdx.x;

    if (blockIdx.x < 16) {
        // ---- qconv: per (b,g) GEMM 128o x 64p, K=32; q scaled by log2e ----
        float* Ws = sm + QC_WS;
        float* Xs = sm + QC_XS;
        float* Os = sm + QC_OS;
        int pt = blockIdx.x;
        #pragma unroll
        for (int u = 0; u < 16; u++) {
            int e = t + 256*u;
            Ws[(e >> 5)*33 + (e & 31)] = wq[g*4096 + e];
        }
        #pragma unroll
        for (int u = 0; u < 8; u++) {
            int e = t + 256*u;
            int k = e >> 6, p = e & 63;
            Xs[e] = x[((b*NG + g)*32 + k)*1024 + pt*64 + p];
        }
        __syncthreads();

        int to = t >> 4, tp = t & 15;
        int o0 = to*8, p0 = tp*4;
        u64 a[8][2];
        #pragma unroll
        for (int i = 0; i < 8; i++) {
            float bi = bq[g*128 + o0 + i];
            a[i][0] = pk2(bi, bi); a[i][1] = a[i][0];
        }
        #pragma unroll 4
        for (int k = 0; k < 32; k++) {
            ulonglong2 xv = *(const ulonglong2*)(Xs + k*64 + p0);
            #pragma unroll
            for (int i = 0; i < 8; i++) {
                float w = Ws[(o0 + i)*33 + k];
                u64 w2 = pk2(w, w);
                FMA2(a[i][0], w2, xv.x);
                FMA2(a[i][1], w2, xv.y);
            }
        }
        const float L2E = 1.4426950408889634f;
        #pragma unroll
        for (int i = 0; i < 8; i++)
            #pragma unroll
            for (int j = 0; j < 2; j++) {
                float lo, hi; up2(a[i][j], lo, hi);
                Os[(p0 + 2*j    )*132 + o0 + i] = lo * L2E;
                Os[(p0 + 2*j + 1)*132 + o0 + i] = hi * L2E;
            }
        __syncthreads();
        #pragma unroll
        for (int u = 0; u < 8; u++) {
            int e = t + 256*u;
            int p = e >> 5, o4 = e & 31;
            float4 v = *(const float4*)(Os + p*132 + o4*4);
            *(float4*)(g_q + (long)(b*1024 + pt*64 + p)*1024 + g*128 + o4*4) = v;
        }
    } else {
        // ---- kv conv: per (b,g) GEMM 64o x 128p on padded grid ----
        float* Ws = sm + KV_WS;
        float* Xs = sm + KV_XS;
        float* bs = sm + KV_BS;
        int pt = blockIdx.x - 16;
        #pragma unroll
        for (int u = 0; u < 8; u++) {
            int e = t + 256*u;
            int o = e >> 5, k = e & 31;
            Ws[o*33 + k] = (o < 32) ? wk[g*1024 + o*32 + k] : wv[g*1024 + (o-32)*32 + k];
        }
        if (t < 64) bs[t] = (t < 32) ? bk[g*32 + t] : bv[g*32 + t - 32];
        #pragma unroll
        for (int u = 0; u < 16; u++) {
            int e = t + 256*u;
            int k = e >> 7, p = e & 127;
            int sp = pt*128 + p;
            float v = 0.f;
            if (sp < NPP) {
                int sy = sp / HP, sx = sp - sy*HP;
                int iy = sy - PD, ix = sx - PD;
                if (iy >= 0 && iy < HH && ix >= 0 && ix < WW)
                    v = x[((b*NG + g)*32 + k)*1024 + iy*32 + ix];
            }
            Xs[k*128 + p] = v;
        }
        __syncthreads();

        int to = t >> 4, tp = t & 15;
        int o0 = to*4, p0 = tp*8;
        u64 acc[4][4];
        #pragma unroll
        for (int oi = 0; oi < 4; oi++) {
            float bi = bs[o0 + oi];
            u64 b2 = pk2(bi, bi);
            #pragma unroll
            for (int pp = 0; pp < 4; pp++) acc[oi][pp] = b2;
        }
        #pragma unroll 4
        for (int k = 0; k < 32; k++) {
            ulonglong2 xa = *(const ulonglong2*)(Xs + k*128 + p0);
            ulonglong2 xb = *(const ulonglong2*)(Xs + k*128 + p0 + 4);
            u64 xx[4] = {xa.x, xa.y, xb.x, xb.y};
            float wv4[4] = {Ws[(o0+0)*33 + k], Ws[(o0+1)*33 + k],
                            Ws[(o0+2)*33 + k], Ws[(o0+3)*33 + k]};
            #pragma unroll
            for (int oi = 0; oi < 4; oi++) {
                u64 w2 = pk2(wv4[oi], wv4[oi]);
                #pragma unroll
                for (int pp = 0; pp < 4; pp++) FMA2(acc[oi][pp], w2, xx[pp]);
            }
        }
        #pragma unroll
        for (int pp = 0; pp < 4; pp++)
            #pragma unroll
            for (int hf = 0; hf < 2; hf++) {
                int sp = pt*128 + p0 + pp*2 + hf;
                if (sp < NPP) {
                    long base = (long)(b*NPP + sp)*256 + g;
                    #pragma unroll
                    for (int oi = 0; oi < 4; oi++) {
                        int o = o0 + oi;
                        float lo, hi; up2(acc[oi][pp], lo, hi);
                        float val = hf ? hi : lo;
                        if (o < 32) g_k[base + o*8] = val;
                        else        g_v[base + (o-32)*8] = val;
                    }
                }
            }
    }
}

// ================= attention =================
// S-GEMM: warp w covers cols [w*64, w*64+64); lane tile 8 rows x 4 cols x 2 passes.
// Pass p col base: w*64 + p*32 + (tx&7)*4. K LDS128 = 8 distinct 16B = 1 phase.
__device__ __forceinline__ void sgemm_warp(float* Ks, const float* qs, float* mb,
                                           int w, int tx) {
    int r0 = (tx >> 3) * 8;
    int c0 = w*64 + (tx & 7)*4;      // pass 0
    int c1 = c0 + 32;                // pass 1
    bool v0 = (c0 < NM), v1 = (c1 < NM);      // real cols
    bool a1 = (c1 < VPAD);                    // pass1 must store (w6 pass1 inactive)
    int lc1 = a1 ? c1 : 0;                    // safe load addr
    u64 acc[8][4];                   // [row][p0lo,p0hi,p1lo,p1hi]
    #pragma unroll
    for (int i = 0; i < 8; i++)
        #pragma unroll
        for (int j = 0; j < 4; j++) acc[i][j] = 0ull;
    #pragma unroll 4
    for (int cc = 0; cc < 32; cc++) {
        ulonglong2 k0 = *(const ulonglong2*)(Ks + cc*MSK + c0);
        ulonglong2 k1 = *(const ulonglong2*)(Ks + cc*MSK + lc1);
        float4 qa = *(const float4*)(qs + cc*32 + r0);
        float4 qb = *(const float4*)(qs + cc*32 + r0 + 4);
        float qv[8] = {qa.x, qa.y, qa.z, qa.w, qb.x, qb.y, qb.z, qb.w};
        #pragma unroll
        for (int i = 0; i < 8; i++) {
            u64 q2 = pk2(qv[i], qv[i]);
            FMA2(acc[i][0], q2, k0.x);
            FMA2(acc[i][1], q2, k0.y);
            FMA2(acc[i][2], q2, k1.x);
            FMA2(acc[i][3], q2, k1.y);
        }
    }
    // epilogue: exp (base-2; log2e folded into q) + row partial sums; zero pads
    #pragma unroll
    for (int i = 0; i < 8; i++) {
        float rsum = 0.f;
        float l0, h0, l1, h1;
        up2(acc[i][0], l0, h0); up2(acc[i][1], l1, h1);
        float e0 = ex2(l0), e1 = ex2(h0), e2 = ex2(l1), e3 = ex2(h1);
        if (v0) rsum += e0 + e1 + e2 + e3;
        u64 s0 = v0 ? pk2(e0, e1) : 0ull;
        u64 s1 = v0 ? pk2(e2, e3) : 0ull;
        *(ulonglong2*)(Ks + (r0 + i)*MSK + c0) = make_ulonglong2(s0, s1);
        up2(acc[i][2], l0, h0); up2(acc[i][3], l1, h1);
        e0 = ex2(l0); e1 = ex2(h0); e2 = ex2(l1); e3 = ex2(h1);
        if (v1) rsum += e0 + e1 + e2 + e3;
        if (a1) {
            u64 t0 = v1 ? pk2(e0, e1) : 0ull;
            u64 t1 = v1 ? pk2(e2, e3) : 0ull;
            *(ulonglong2*)(Ks + (r0 + i)*MSK + c1) = make_ulonglong2(t0, t1);
        }
        rsum += __shfl_xor_sync(0xffffffffu, rsum, 1);
        rsum += __shfl_xor_sync(0xffffffffu, rsum, 2);
        rsum += __shfl_xor_sync(0xffffffffu, rsum, 4);
        if ((tx & 7) == 0) mb[w*32 + r0 + i] = rsum;
    }
}

__global__ void __launch_bounds__(256, 2) attn_kernel(const float* __restrict__ rel_h,
                                                      const float* __restrict__ rel_w,
                                                      float* __restrict__ out) {
    extern __shared__ float sm[];
    float* Ks   = sm + SM_KS;    // [32 c][MSK] -> S/E in place
    float* Vs   = sm + SM_VS;    // transposed: [m][MSVT] (m = 0..415)
    float* qs   = sm + SM_QS;    // [c][32 r]
    float* mb   = sm + SM_MB;    // [8 w][32 r]
    float* rinv = sm + SM_RI;
    float* Rs   = Ks + 8*MSK;    // O-GEMM partials, reuses dead S rows 8..13

    int bp = blockIdx.x;
    int b = bp >> 10, p = bp & 1023;
    int px = p >> 5, py = p & 31;
    int t = threadIdx.x;
    int tx = t & 31, ty = t >> 5;

    // stage q: qs[c*32 + hh*8 + g]
    {
        float4 qv = ((const float4*)(g_q + (long)bp*1024))[t];
        int s = t*4;
        int g = s >> 7, hh = (s >> 5) & 3, c0 = s & 31;
        qs[(c0+0)*32 + hh*8 + g] = qv.x;
        qs[(c0+1)*32 + hh*8 + g] = qv.y;
        qs[(c0+2)*32 + hh*8 + g] = qv.z;
        qs[(c0+3)*32 + hh*8 + g] = qv.w;
    }

    // stage K(+rel) [c][m], V transposed [m][c]; both STS conflict-free
    {
        int c = t >> 3, gq = t & 7;
        float rh[KS];
        #pragma unroll
        for (int u = 0; u < KS; u++)
            rh[u] = (c < 16) ? rel_h[c*56 + gq*7 + u] : rel_w[(c - 16)*56 + gq*7 + u];
        const float* kbase = g_k + ((long)(b*HP + px)*HP + py)*256 + t;
        const float* vbase = g_v + ((long)(b*HP + px)*HP + py)*256 + t;
        for (int i = 0; i < KS; i++) {
            #pragma unroll
            for (int j = 0; j < KS; j++) {
                int m = gq*49 + i*7 + j;
                int off = (i*HP + j)*256;
                float rel = (c < 16) ? rh[i] : rh[j];
                Ks[c*MSK + m] = kbase[off] + rel;
                Vs[m*MSVT + c] = vbase[off];
            }
        }
        // zero V pad rows 392..415
        for (int e = t; e < (VPAD - NM)*MSVT; e += 256) Vs[NM*MSVT + e] = 0.f;
    }
    __syncthreads();

    // S = q^T K with fused exp + row partial sums; pad cols 392..415 stored 0
    if (ty < 7) sgemm_warp(Ks, qs, mb, ty, tx);
    __syncthreads();

    if (t < 32) {
        float s = 0.f;
        #pragma unroll
        for (int w = 0; w < 7; w++) s += mb[w*32 + t];
        rinv[t] = 1.f / s;
    }
    __syncthreads();

    // collapse heads over padded range (pads are 0): Ag[g][0..415]
    for (int idx = t; idx < 8*104; idx += 256) {
        int g = idx / 104;
        int m4 = (idx - g*104)*4;
        float r0 = rinv[g], r1 = rinv[8 + g], r2 = rinv[16 + g], r3 = rinv[24 + g];
        float4 a0 = *(const float4*)(Ks + g*MSK + m4);
        float4 a1 = *(const float4*)(Ks + (8 + g)*MSK + m4);
        float4 a2 = *(const float4*)(Ks + (16 + g)*MSK + m4);
        float4 a3 = *(const float4*)(Ks + (24 + g)*MSK + m4);
        float4 r;
        r.x = a0.x*r0 + a1.x*r1 + a2.x*r2 + a3.x*r3;
        r.y = a0.y*r0 + a1.y*r1 + a2.y*r2 + a3.y*r3;
        r.z = a0.z*r0 + a1.z*r1 + a2.z*r2 + a3.z*r3;
        r.w = a0.w*r0 + a1.w*r1 + a2.w*r2 + a3.w*r3;
        *(float4*)(Ks + g*MSK + m4) = r;
    }
    __syncthreads();

    // O-GEMM split-m: warp w handles 13 f4 chunks; thread c=tx does all 8 g
    {
        u64 og[8];
        #pragma unroll
        for (int g = 0; g < 8; g++) og[g] = 0ull;
        int c = tx, w = ty;
        #pragma unroll
        for (int i = 0; i < 13; i++) {
            int mq = (w*13 + i)*4;
            float v0 = Vs[(mq+0)*MSVT + c];
            float v1 = Vs[(mq+1)*MSVT + c];
            float v2 = Vs[(mq+2)*MSVT + c];
            float v3 = Vs[(mq+3)*MSVT + c];
            u64 vx = pk2(v0, v1), vy = pk2(v2, v3);
            #pragma unroll
            for (int g = 0; g < 8; g++) {
                ulonglong2 a = *(const ulonglong2*)(Ks + g*MSK + mq);
                FMA2(og[g], a.x, vx);
                FMA2(og[g], a.y, vy);
            }
        }
        #pragma unroll
        for (int g = 0; g < 8; g++) {
            float lo, hi; up2(og[g], lo, hi);
            Rs[w*264 + g*33 + c] = lo + hi;
        }
    }
    __syncthreads();

    // final reduce over 8 warps + scrambled store: out[b, g*32+px, py, c]
    {
        int c = tx, g = ty;
        float s = 0.f;
        #pragma unroll
        for (int w = 0; w < 8; w++) s += Rs[w*264 + g*33 + c];
        out[b*262144 + (g*32 + px)*1024 + py*32 + c] = s;
    }
}

// ---------------- launch ----------------
extern "C" void kernel_launch(void* const* d_in, const int* in_sizes, int n_in,
                              void* d_out, int out_size) {
    const float* x   = (const float*)d_in[0];
    const float* wq  = (const float*)d_in[1];
    const float* bq  = (const float*)d_in[2];
    const float* wk  = (const float*)d_in[3];
    const float* bk  = (const float*)d_in[4];
    const float* wv  = (const float*)d_in[5];
    const float* bv  = (const float*)d_in[6];
    const float* rlh = (const float*)d_in[7];
    const float* rlw = (const float*)d_in[8];
    float* out = (float*)d_out;

    cudaFuncSetAttribute(conv_kernel, cudaFuncAttributeMaxDynamicSharedMemorySize, CONV_SMEM);
    cudaFuncSetAttribute(attn_kernel, cudaFuncAttributeMaxDynamicSharedMemorySize, ATTN_SMEM);

    conv_kernel<<<dim3(28, 8, 4), 256, CONV_SMEM>>>(x, wq, bq, wk, bk, wv, bv);
    attn_kernel<<<NB*NPIX, 256, ATTN_SMEM>>>(rlh, rlw, out);
}

// round 10
// speedup vs baseline: 2.4703x; 1.0288x over previous
#include <cuda_runtime.h>

#define NB 4
#define NG 8
#define HH 32
#define WW 32
#define KS 7
#define PD 3
#define HP 38
#define NPP 1444      // HP*HP
#define NM 392
#define VPAD 416      // padded S cols (stored zeros; collapse reads only m<392)
#define MSK 424       // mod32=8: K-staging STS conflict-free; mult of 4
#define NPIX 1024

#define SM_KS  0
#define SM_AGT (32*MSK)            // 13568 ; Agt[ij*64 + g*8 + g'] (3136)
#define SM_QS  (SM_AGT + 3136)     // 16704
#define SM_MB  (SM_QS + 1024)      // 17728  [8w][32r]
#define SM_RI  (SM_MB + 256)       // 17984
#define ATTN_SMEM ((SM_RI + 32)*4) // 72064 B -> 2 CTA/SM (regs bind), big L1$ left

// conv kernel smem (qconv view)
#define QC_WS 0                    // [128 o][33]
#define QC_XS (128*33)             // [32 k][64 p]
#define QC_OS (QC_XS + 32*64)      // [64 p][132]
#define CONV_SMEM ((QC_OS + 64*132)*4)   // 58880 B
// kv view
#define KV_WS 0                    // [64 o][33]
#define KV_XS (64*33)              // [32 k][128 p]
#define KV_BS (KV_XS + 32*128)     // [64]

__device__ float g_q[NB*NPIX*1024];   // [b][p][g*128 + hh*32 + c]  (q * log2e)
__device__ float g_k[NB*NPP*256];     // [b][sp][c*8+g]
__device__ float g_v[NB*NPP*256];

typedef unsigned long long u64;
__device__ __forceinline__ u64 pk2(float a, float b) {
    u64 r; asm("mov.b64 %0, {%1,%2};" : "=l"(r) : "f"(a), "f"(b)); return r;
}
__device__ __forceinline__ void up2(u64 v, float& a, float& b) {
    asm("mov.b64 {%0,%1}, %2;" : "=f"(a), "=f"(b) : "l"(v));
}
#define FMA2(d,a,b) asm("fma.rn.f32x2 %0, %1, %2, %0;" : "+l"(d) : "l"(a), "l"(b))
__device__ __forceinline__ float ex2(float x) {
    float r; asm("ex2.approx.f32 %0, %1;" : "=f"(r) : "f"(x)); return r;
}

// ================= fused conv kernel =================
__global__ void __launch_bounds__(256) conv_kernel(const float* __restrict__ x,
                                                   const float* __restrict__ wq,
                                                   const float* __restrict__ bq,
                                                   const float* __restrict__ wk,
                                                   const float* __restrict__ bk,
                                                   const float* __restrict__ wv,
                                                   const float* __restrict__ bv) {
    extern __shared__ float sm[];
    int g = blockIdx.y, b = blockIdx.z;
    int t = threadIdx.x;

    if (blockIdx.x < 16) {
        // ---- qconv: per (b,g) GEMM 128o x 64p, K=32; q scaled by log2e ----
        float* Ws = sm + QC_WS;
        float* Xs = sm + QC_XS;
        float* Os = sm + QC_OS;
        int pt = blockIdx.x;
        #pragma unroll
        for (int u = 0; u < 16; u++) {
            int e = t + 256*u;
            Ws[(e >> 5)*33 + (e & 31)] = wq[g*4096 + e];
        }
        #pragma unroll
        for (int u = 0; u < 8; u++) {
            int e = t + 256*u;
            int k = e >> 6, p = e & 63;
            Xs[e] = x[((b*NG + g)*32 + k)*1024 + pt*64 + p];
        }
        __syncthreads();

        int to = t >> 4, tp = t & 15;
        int o0 = to*8, p0 = tp*4;
        u64 a[8][2];
        #pragma unroll
        for (int i = 0; i < 8; i++) {
            float bi = bq[g*128 + o0 + i];
            a[i][0] = pk2(bi, bi); a[i][1] = a[i][0];
        }
        #pragma unroll 4
        for (int k = 0; k < 32; k++) {
            ulonglong2 xv = *(const ulonglong2*)(Xs + k*64 + p0);
            #pragma unroll
            for (int i = 0; i < 8; i++) {
                float w = Ws[(o0 + i)*33 + k];
                u64 w2 = pk2(w, w);
                FMA2(a[i][0], w2, xv.x);
                FMA2(a[i][1], w2, xv.y);
            }
        }
        const float L2E = 1.4426950408889634f;
        #pragma unroll
        for (int i = 0; i < 8; i++)
            #pragma unroll
            for (int j = 0; j < 2; j++) {
                float lo, hi; up2(a[i][j], lo, hi);
                Os[(p0 + 2*j    )*132 + o0 + i] = lo * L2E;
                Os[(p0 + 2*j + 1)*132 + o0 + i] = hi * L2E;
            }
        __syncthreads();
        #pragma unroll
        for (int u = 0; u < 8; u++) {
            int e = t + 256*u;
            int p = e >> 5, o4 = e & 31;
            float4 v = *(const float4*)(Os + p*132 + o4*4);
            *(float4*)(g_q + (long)(b*1024 + pt*64 + p)*1024 + g*128 + o4*4) = v;
        }
    } else {
        // ---- kv conv: per (b,g) GEMM 64o x 128p on padded grid ----
        float* Ws = sm + KV_WS;
        float* Xs = sm + KV_XS;
        float* bs = sm + KV_BS;
        int pt = blockIdx.x - 16;
        #pragma unroll
        for (int u = 0; u < 8; u++) {
            int e = t + 256*u;
            int o = e >> 5, k = e & 31;
            Ws[o*33 + k] = (o < 32) ? wk[g*1024 + o*32 + k] : wv[g*1024 + (o-32)*32 + k];
        }
        if (t < 64) bs[t] = (t < 32) ? bk[g*32 + t] : bv[g*32 + t - 32];
        #pragma unroll
        for (int u = 0; u < 16; u++) {
            int e = t + 256*u;
            int k = e >> 7, p = e & 127;
            int sp = pt*128 + p;
            float v = 0.f;
            if (sp < NPP) {
                int sy = sp / HP, sx = sp - sy*HP;
                int iy = sy - PD, ix = sx - PD;
                if (iy >= 0 && iy < HH && ix >= 0 && ix < WW)
                    v = x[((b*NG + g)*32 + k)*1024 + iy*32 + ix];
            }
            Xs[k*128 + p] = v;
        }
        __syncthreads();

        int to = t >> 4, tp = t & 15;
        int o0 = to*4, p0 = tp*8;
        u64 acc[4][4];
        #pragma unroll
        for (int oi = 0; oi < 4; oi++) {
            float bi = bs[o0 + oi];
            u64 b2 = pk2(bi, bi);
            #pragma unroll
            for (int pp = 0; pp < 4; pp++) acc[oi][pp] = b2;
        }
        #pragma unroll 4
        for (int k = 0; k < 32; k++) {
            ulonglong2 xa = *(const ulonglong2*)(Xs + k*128 + p0);
            ulonglong2 xb = *(const ulonglong2*)(Xs + k*128 + p0 + 4);
            u64 xx[4] = {xa.x, xa.y, xb.x, xb.y};
            float wv4[4] = {Ws[(o0+0)*33 + k], Ws[(o0+1)*33 + k],
                            Ws[(o0+2)*33 + k], Ws[(o0+3)*33 + k]};
            #pragma unroll
            for (int oi = 0; oi < 4; oi++) {
                u64 w2 = pk2(wv4[oi], wv4[oi]);
                #pragma unroll
                for (int pp = 0; pp < 4; pp++) FMA2(acc[oi][pp], w2, xx[pp]);
            }
        }
        #pragma unroll
        for (int pp = 0; pp < 4; pp++)
            #pragma unroll
            for (int hf = 0; hf < 2; hf++) {
                int sp = pt*128 + p0 + pp*2 + hf;
                if (sp < NPP) {
                    long base = (long)(b*NPP + sp)*256 + g;
                    #pragma unroll
                    for (int oi = 0; oi < 4; oi++) {
                        int o = o0 + oi;
                        float lo, hi; up2(acc[oi][pp], lo, hi);
                        float val = hf ? hi : lo;
                        if (o < 32) g_k[base + o*8] = val;
                        else        g_v[base + (o-32)*8] = val;
                    }
                }
            }
    }
}

// ================= attention =================
// S-GEMM: warp w covers cols [w*64, w*64+64); lane tile 8 rows x 4 cols x 2 passes.
__device__ __forceinline__ void sgemm_warp(float* Ks, const float* qs, float* mb,
                                           int w, int tx) {
    int r0 = (tx >> 3) * 8;
    int c0 = w*64 + (tx & 7)*4;      // pass 0
    int c1 = c0 + 32;                // pass 1
    bool v0 = (c0 < NM), v1 = (c1 < NM);      // real cols
    bool a1 = (c1 < VPAD);                    // pass1 must store (w6 pass1 inactive)
    int lc1 = a1 ? c1 : 0;                    // safe load addr
    u64 acc[8][4];                   // [row][p0lo,p0hi,p1lo,p1hi]
    #pragma unroll
    for (int i = 0; i < 8; i++)
        #pragma unroll
        for (int j = 0; j < 4; j++) acc[i][j] = 0ull;
    #pragma unroll 4
    for (int cc = 0; cc < 32; cc++) {
        ulonglong2 k0 = *(const ulonglong2*)(Ks + cc*MSK + c0);
        ulonglong2 k1 = *(const ulonglong2*)(Ks + cc*MSK + lc1);
        float4 qa = *(const float4*)(qs + cc*32 + r0);
        float4 qb = *(const float4*)(qs + cc*32 + r0 + 4);
        float qv[8] = {qa.x, qa.y, qa.z, qa.w, qb.x, qb.y, qb.z, qb.w};
        #pragma unroll
        for (int i = 0; i < 8; i++) {
            u64 q2 = pk2(qv[i], qv[i]);
            FMA2(acc[i][0], q2, k0.x);
            FMA2(acc[i][1], q2, k0.y);
            FMA2(acc[i][2], q2, k1.x);
            FMA2(acc[i][3], q2, k1.y);
        }
    }
    // epilogue: exp (base-2; log2e folded into q) + row partial sums; zero pads
    #pragma unroll
    for (int i = 0; i < 8; i++) {
        float rsum = 0.f;
        float l0, h0, l1, h1;
        up2(acc[i][0], l0, h0); up2(acc[i][1], l1, h1);
        float e0 = ex2(l0), e1 = ex2(h0), e2 = ex2(l1), e3 = ex2(h1);
        if (v0) rsum += e0 + e1 + e2 + e3;
        u64 s0 = v0 ? pk2(e0, e1) : 0ull;
        u64 s1 = v0 ? pk2(e2, e3) : 0ull;
        *(ulonglong2*)(Ks + (r0 + i)*MSK + c0) = make_ulonglong2(s0, s1);
        up2(acc[i][2], l0, h0); up2(acc[i][3], l1, h1);
        e0 = ex2(l0); e1 = ex2(h0); e2 = ex2(l1); e3 = ex2(h1);
        if (v1) rsum += e0 + e1 + e2 + e3;
        if (a1) {
            u64 t0 = v1 ? pk2(e0, e1) : 0ull;
            u64 t1 = v1 ? pk2(e2, e3) : 0ull;
            *(ulonglong2*)(Ks + (r0 + i)*MSK + c1) = make_ulonglong2(t0, t1);
        }
        rsum += __shfl_xor_sync(0xffffffffu, rsum, 1);
        rsum += __shfl_xor_sync(0xffffffffu, rsum, 2);
        rsum += __shfl_xor_sync(0xffffffffu, rsum, 4);
        if ((tx & 7) == 0) mb[w*32 + r0 + i] = rsum;
    }
}

__global__ void __launch_bounds__(256, 2) attn_kernel(const float* __restrict__ rel_h,
                                                      const float* __restrict__ rel_w,
                                                      const float* __restrict__ gv,
                                                      float* __restrict__ out) {
    extern __shared__ float sm[];
    float* Ks   = sm + SM_KS;    // [32 c][MSK] -> E in place
    float* Agt  = sm + SM_AGT;   // [ij][g][g'] 49x8x8
    float* qs   = sm + SM_QS;    // [c][32 r]
    float* mb   = sm + SM_MB;    // [8 w][32 r]
    float* rinv = sm + SM_RI;
    float* Rs   = Ks;            // O-GEMM partials reuse Ks (E dead by then)

    int bp = blockIdx.x;
    int b = bp >> 10, p = bp & 1023;
    int px = p >> 5, py = p & 31;
    int t = threadIdx.x;
    int tx = t & 31, ty = t >> 5;

    // stage q: qs[c*32 + hh*8 + g]
    {
        float4 qv = ((const float4*)(g_q + (long)bp*1024))[t];
        int s = t*4;
        int g = s >> 7, hh = (s >> 5) & 3, c0 = s & 31;
        qs[(c0+0)*32 + hh*8 + g] = qv.x;
        qs[(c0+1)*32 + hh*8 + g] = qv.y;
        qs[(c0+2)*32 + hh*8 + g] = qv.z;
        qs[(c0+3)*32 + hh*8 + g] = qv.w;
    }

    // stage K(+rel) [c][m] only; STS conflict-free (MSK%32==8)
    {
        int c = t >> 3, gq = t & 7;
        float rh[KS];
        #pragma unroll
        for (int u = 0; u < KS; u++)
            rh[u] = (c < 16) ? rel_h[c*56 + gq*7 + u] : rel_w[(c - 16)*56 + gq*7 + u];
        const float* kbase = g_k + ((long)(b*HP + px)*HP + py)*256 + t;
        for (int i = 0; i < KS; i++) {
            #pragma unroll
            for (int j = 0; j < KS; j++) {
                int m = gq*49 + i*7 + j;
                int off = (i*HP + j)*256;
                float rel = (c < 16) ? rh[i] : rh[j];
                Ks[c*MSK + m] = kbase[off] + rel;
            }
        }
    }
    __syncthreads();

    // S = q^T K with fused exp + row partial sums
    if (ty < 7) sgemm_warp(Ks, qs, mb, ty, tx);
    __syncthreads();

    if (t < 32) {
        float s = 0.f;
        #pragma unroll
        for (int w = 0; w < 7; w++) s += mb[w*32 + t];
        rinv[t] = 1.f / s;
    }
    __syncthreads();

    // collapse heads into transposed layout: Agt[ij*64 + g*8 + g'] =
    //   sum_h E[h*8+g][g'*49+ij] * rinv[h*8+g]   (reads only m<392)
    for (int idx = t; idx < 3136; idx += 256) {
        int ij = idx >> 6;
        int rem = idx & 63;
        int g = rem >> 3, gp = rem & 7;
        int m = gp*49 + ij;
        float s = Ks[g*MSK + m]        * rinv[g]
                + Ks[(8+g)*MSK + m]    * rinv[8+g]
                + Ks[(16+g)*MSK + m]   * rinv[16+g]
                + Ks[(24+g)*MSK + m]   * rinv[24+g];
        Agt[idx] = s;
    }
    __syncthreads();

    // O-GEMM: V read directly from gmem (coalesced, consumed once).
    // warp w covers ij = 8k + w; lane c: og[g] += sum_{g'} Agt[ij][g][g'] * V[c][g',ij]
    {
        u64 og[8];
        #pragma unroll
        for (int g = 0; g < 8; g++) og[g] = 0ull;
        int c = tx, w = ty;
        const float* vb = gv + ((long)(b*HP + px)*HP + py)*256 + c*8;
        #pragma unroll
        for (int k = 0; k < 7; k++) {
            int ij = k*8 + w;
            if (ij < 49) {
                int i = ij / 7, j = ij - i*7;
                const float4* vp = (const float4*)(vb + (i*HP + j)*256);
                float4 va = vp[0], vbq = vp[1];
                u64 v0 = pk2(va.x, va.y), v1 = pk2(va.z, va.w);
                u64 v2 = pk2(vbq.x, vbq.y), v3 = pk2(vbq.z, vbq.w);
                const float* ab = Agt + ij*64;
                #pragma unroll
                for (int g = 0; g < 8; g++) {
                    ulonglong2 a0 = *(const ulonglong2*)(ab + g*8);
                    ulonglong2 a1 = *(const ulonglong2*)(ab + g*8 + 4);
                    FMA2(og[g], a0.x, v0);
                    FMA2(og[g], a0.y, v1);
                    FMA2(og[g], a1.x, v2);
                    FMA2(og[g], a1.y, v3);
                }
            }
        }
        __syncthreads();   // ensure all Agt/E reads done before Rs overwrites Ks
        #pragma unroll
        for (int g = 0; g < 8; g++) {
            float lo, hi; up2(og[g], lo, hi);
            Rs[w*264 + g*33 + c] = lo + hi;
        }
    }
    __syncthreads();

    // final reduce over 8 warps + scrambled store: out[b, g*32+px, py, c]
    {
        int c = tx, g = ty;
        float s = 0.f;
        #pragma unroll
        for (int w = 0; w < 8; w++) s += Rs[w*264 + g*33 + c];
        out[b*262144 + (g*32 + px)*1024 + py*32 + c] = s;
    }
}

// ---------------- launch ----------------
extern "C" void kernel_launch(void* const* d_in, const int* in_sizes, int n_in,
                              void* d_out, int out_size) {
    const float* x   = (const float*)d_in[0];
    const float* wq  = (const float*)d_in[1];
    const float* bq  = (const float*)d_in[2];
    const float* wk  = (const float*)d_in[3];
    const float* bk  = (const float*)d_in[4];
    const float* wv  = (const float*)d_in[5];
    const float* bv  = (const float*)d_in[6];
    const float* rlh = (const float*)d_in[7];
    const float* rlw = (const float*)d_in[8];
    float* out = (float*)d_out;

    cudaFuncSetAttribute(conv_kernel, cudaFuncAttributeMaxDynamicSharedMemorySize, CONV_SMEM);
    cudaFuncSetAttribute(attn_kernel, cudaFuncAttributeMaxDynamicSharedMemorySize, ATTN_SMEM);

    conv_kernel<<<dim3(28, 8, 4), 256, CONV_SMEM>>>(x, wq, bq, wk, bk, wv, bv);

    // fetch g_v device address host-side once per launch call (cheap, capture-safe)
    float* gv_ptr = nullptr;
    cudaGetSymbolAddress((void**)&gv_ptr, g_v);
    attn_kernel<<<NB*NPIX, 256, ATTN_SMEM>>>(rlh, rlw, gv_ptr, out);
}

// round 11
// speedup vs baseline: 2.6003x; 1.0526x over previous
#include <cuda_runtime.h>

#define NB 4
#define NG 8
#define HH 32
#define WW 32
#define KS 7
#define PD 3
#define HP 38
#define NPP 1444      // HP*HP
#define NM 392
#define VPAD 416      // padded S cols (stored zeros; collapse reads only m<392)
#define MSK 424       // mod32=8: K-staging STS conflict-free; mult of 4
#define NPIX 1024

#define SM_KS  0
#define SM_AGT (32*MSK)            // 13568 ; Agt[ij*64 + g*8 + g'] (3136)
#define SM_QS  (SM_AGT + 3136)     // 16704
#define SM_MB  (SM_QS + 1024)      // 17728  [8w][32r]
#define SM_RI  (SM_MB + 256)       // 17984
#define ATTN_SMEM ((SM_RI + 32)*4) // 72064 B -> 3 CTA/SM (216KB of 228KB)

// conv kernel smem (qconv view)
#define QC_WS 0                    // [128 o][33]
#define QC_XS (128*33)             // [32 k][64 p]
#define QC_OS (QC_XS + 32*64)      // [64 p][132]
#define CONV_SMEM ((QC_OS + 64*132)*4)   // 58880 B
// kv view
#define KV_WS 0                    // [64 o][33]
#define KV_XS (64*33)              // [32 k][128 p]
#define KV_BS (KV_XS + 32*128)     // [64]

__device__ float g_q[NB*NPIX*1024];   // [b][p][g*128 + hh*32 + c]  (q * log2e)
__device__ float g_k[NB*NPP*256];     // [b][sp][c*8+g]
__device__ float g_v[NB*NPP*256];

typedef unsigned long long u64;
__device__ __forceinline__ u64 pk2(float a, float b) {
    u64 r; asm("mov.b64 %0, {%1,%2};" : "=l"(r) : "f"(a), "f"(b)); return r;
}
__device__ __forceinline__ void up2(u64 v, float& a, float& b) {
    asm("mov.b64 {%0,%1}, %2;" : "=f"(a), "=f"(b) : "l"(v));
}
#define FMA2(d,a,b) asm("fma.rn.f32x2 %0, %1, %2, %0;" : "+l"(d) : "l"(a), "l"(b))
__device__ __forceinline__ float ex2(float x) {
    float r; asm("ex2.approx.f32 %0, %1;" : "=f"(r) : "f"(x)); return r;
}

// ================= fused conv kernel =================
__global__ void __launch_bounds__(256) conv_kernel(const float* __restrict__ x,
                                                   const float* __restrict__ wq,
                                                   const float* __restrict__ bq,
                                                   const float* __restrict__ wk,
                                                   const float* __restrict__ bk,
                                                   const float* __restrict__ wv,
                                                   const float* __restrict__ bv) {
    extern __shared__ float sm[];
    int g = blockIdx.y, b = blockIdx.z;
    int t = threadIdx.x;

    if (blockIdx.x < 16) {
        // ---- qconv: per (b,g) GEMM 128o x 64p, K=32; q scaled by log2e ----
        float* Ws = sm + QC_WS;
        float* Xs = sm + QC_XS;
        float* Os = sm + QC_OS;
        int pt = blockIdx.x;
        #pragma unroll
        for (int u = 0; u < 16; u++) {
            int e = t + 256*u;
            Ws[(e >> 5)*33 + (e & 31)] = wq[g*4096 + e];
        }
        #pragma unroll
        for (int u = 0; u < 8; u++) {
            int e = t + 256*u;
            int k = e >> 6, p = e & 63;
            Xs[e] = x[((b*NG + g)*32 + k)*1024 + pt*64 + p];
        }
        __syncthreads();

        int to = t >> 4, tp = t & 15;
        int o0 = to*8, p0 = tp*4;
        u64 a[8][2];
        #pragma unroll
        for (int i = 0; i < 8; i++) {
            float bi = bq[g*128 + o0 + i];
            a[i][0] = pk2(bi, bi); a[i][1] = a[i][0];
        }
        #pragma unroll 4
        for (int k = 0; k < 32; k++) {
            ulonglong2 xv = *(const ulonglong2*)(Xs + k*64 + p0);
            #pragma unroll
            for (int i = 0; i < 8; i++) {
                float w = Ws[(o0 + i)*33 + k];
                u64 w2 = pk2(w, w);
                FMA2(a[i][0], w2, xv.x);
                FMA2(a[i][1], w2, xv.y);
            }
        }
        const float L2E = 1.4426950408889634f;
        #pragma unroll
        for (int i = 0; i < 8; i++)
            #pragma unroll
            for (int j = 0; j < 2; j++) {
                float lo, hi; up2(a[i][j], lo, hi);
                Os[(p0 + 2*j    )*132 + o0 + i] = lo * L2E;
                Os[(p0 + 2*j + 1)*132 + o0 + i] = hi * L2E;
            }
        __syncthreads();
        #pragma unroll
        for (int u = 0; u < 8; u++) {
            int e = t + 256*u;
            int p = e >> 5, o4 = e & 31;
            float4 v = *(const float4*)(Os + p*132 + o4*4);
            *(float4*)(g_q + (long)(b*1024 + pt*64 + p)*1024 + g*128 + o4*4) = v;
        }
    } else {
        // ---- kv conv: per (b,g) GEMM 64o x 128p on padded grid ----
        float* Ws = sm + KV_WS;
        float* Xs = sm + KV_XS;
        float* bs = sm + KV_BS;
        int pt = blockIdx.x - 16;
        #pragma unroll
        for (int u = 0; u < 8; u++) {
            int e = t + 256*u;
            int o = e >> 5, k = e & 31;
            Ws[o*33 + k] = (o < 32) ? wk[g*1024 + o*32 + k] : wv[g*1024 + (o-32)*32 + k];
        }
        if (t < 64) bs[t] = (t < 32) ? bk[g*32 + t] : bv[g*32 + t - 32];
        #pragma unroll
        for (int u = 0; u < 16; u++) {
            int e = t + 256*u;
            int k = e >> 7, p = e & 127;
            int sp = pt*128 + p;
            float v = 0.f;
            if (sp < NPP) {
                int sy = sp / HP, sx = sp - sy*HP;
                int iy = sy - PD, ix = sx - PD;
                if (iy >= 0 && iy < HH && ix >= 0 && ix < WW)
                    v = x[((b*NG + g)*32 + k)*1024 + iy*32 + ix];
            }
            Xs[k*128 + p] = v;
        }
        __syncthreads();

        int to = t >> 4, tp = t & 15;
        int o0 = to*4, p0 = tp*8;
        u64 acc[4][4];
        #pragma unroll
        for (int oi = 0; oi < 4; oi++) {
            float bi = bs[o0 + oi];
            u64 b2 = pk2(bi, bi);
            #pragma unroll
            for (int pp = 0; pp < 4; pp++) acc[oi][pp] = b2;
        }
        #pragma unroll 4
        for (int k = 0; k < 32; k++) {
            ulonglong2 xa = *(const ulonglong2*)(Xs + k*128 + p0);
            ulonglong2 xb = *(const ulonglong2*)(Xs + k*128 + p0 + 4);
            u64 xx[4] = {xa.x, xa.y, xb.x, xb.y};
            float wv4[4] = {Ws[(o0+0)*33 + k], Ws[(o0+1)*33 + k],
                            Ws[(o0+2)*33 + k], Ws[(o0+3)*33 + k]};
            #pragma unroll
            for (int oi = 0; oi < 4; oi++) {
                u64 w2 = pk2(wv4[oi], wv4[oi]);
                #pragma unroll
                for (int pp = 0; pp < 4; pp++) FMA2(acc[oi][pp], w2, xx[pp]);
            }
        }
        #pragma unroll
        for (int pp = 0; pp < 4; pp++)
            #pragma unroll
            for (int hf = 0; hf < 2; hf++) {
                int sp = pt*128 + p0 + pp*2 + hf;
                if (sp < NPP) {
                    long base = (long)(b*NPP + sp)*256 + g;
                    #pragma unroll
                    for (int oi = 0; oi < 4; oi++) {
                        int o = o0 + oi;
                        float lo, hi; up2(acc[oi][pp], lo, hi);
                        float val = hf ? hi : lo;
                        if (o < 32) g_k[base + o*8] = val;
                        else        g_v[base + (o-32)*8] = val;
                    }
                }
            }
    }
}

// ================= attention =================
// One S-GEMM pass: 8 rows x 4 cols per lane; acc = 16 u64 (fits 3 CTA/SM regs)
__device__ __forceinline__ void sgemm_pass(float* Ks, const float* qs,
                                           int r0, int cb, bool valid, bool active,
                                           float* rsum) {
    int lc = active ? cb : 0;
    u64 acc[8][2];
    #pragma unroll
    for (int i = 0; i < 8; i++) { acc[i][0] = 0ull; acc[i][1] = 0ull; }
    #pragma unroll 4
    for (int cc = 0; cc < 32; cc++) {
        ulonglong2 k = *(const ulonglong2*)(Ks + cc*MSK + lc);
        float4 qa = *(const float4*)(qs + cc*32 + r0);
        float4 qb = *(const float4*)(qs + cc*32 + r0 + 4);
        float qv[8] = {qa.x, qa.y, qa.z, qa.w, qb.x, qb.y, qb.z, qb.w};
        #pragma unroll
        for (int i = 0; i < 8; i++) {
            u64 q2 = pk2(qv[i], qv[i]);
            FMA2(acc[i][0], q2, k.x);
            FMA2(acc[i][1], q2, k.y);
        }
    }
    #pragma unroll
    for (int i = 0; i < 8; i++) {
        float l0, h0, l1, h1;
        up2(acc[i][0], l0, h0); up2(acc[i][1], l1, h1);
        float e0 = ex2(l0), e1 = ex2(h0), e2 = ex2(l1), e3 = ex2(h1);
        if (valid) rsum[i] += e0 + e1 + e2 + e3;
        if (active) {
            u64 s0 = valid ? pk2(e0, e1) : 0ull;
            u64 s1 = valid ? pk2(e2, e3) : 0ull;
            *(ulonglong2*)(Ks + (r0 + i)*MSK + cb) = make_ulonglong2(s0, s1);
        }
    }
}

__device__ __forceinline__ void sgemm_warp(float* Ks, const float* qs, float* mb,
                                           int w, int tx) {
    int r0 = (tx >> 3) * 8;
    int c0 = w*64 + (tx & 7)*4;      // pass 0 cols
    int c1 = c0 + 32;                // pass 1 cols
    float rsum[8];
    #pragma unroll
    for (int i = 0; i < 8; i++) rsum[i] = 0.f;
    sgemm_pass(Ks, qs, r0, c0, c0 < NM, c0 < VPAD, rsum);
    sgemm_pass(Ks, qs, r0, c1, c1 < NM, c1 < VPAD, rsum);
    #pragma unroll
    for (int i = 0; i < 8; i++) {
        float s = rsum[i];
        s += __shfl_xor_sync(0xffffffffu, s, 1);
        s += __shfl_xor_sync(0xffffffffu, s, 2);
        s += __shfl_xor_sync(0xffffffffu, s, 4);
        if ((tx & 7) == 0) mb[w*32 + r0 + i] = s;
    }
}

__global__ void __launch_bounds__(256, 3) attn_kernel(const float* __restrict__ rel_h,
                                                      const float* __restrict__ rel_w,
                                                      const float* __restrict__ gv,
                                                      float* __restrict__ out) {
    extern __shared__ float sm[];
    float* Ks   = sm + SM_KS;    // [32 c][MSK] -> E in place
    float* Agt  = sm + SM_AGT;   // [ij][g][g'] 49x8x8
    float* qs   = sm + SM_QS;    // [c][32 r]
    float* mb   = sm + SM_MB;    // [8 w][32 r]
    float* rinv = sm + SM_RI;
    float* Rs   = Ks;            // O-GEMM partials reuse Ks (E dead by then)

    int bp = blockIdx.x;
    int b = bp >> 10, p = bp & 1023;
    int px = p >> 5, py = p & 31;
    int t = threadIdx.x;
    int tx = t & 31, ty = t >> 5;

    // stage q: qs[c*32 + hh*8 + g]
    {
        float4 qv = ((const float4*)(g_q + (long)bp*1024))[t];
        int s = t*4;
        int g = s >> 7, hh = (s >> 5) & 3, c0 = s & 31;
        qs[(c0+0)*32 + hh*8 + g] = qv.x;
        qs[(c0+1)*32 + hh*8 + g] = qv.y;
        qs[(c0+2)*32 + hh*8 + g] = qv.z;
        qs[(c0+3)*32 + hh*8 + g] = qv.w;
    }

    // stage K(+rel) [c][m]; STS conflict-free (MSK%32==8)
    {
        int c = t >> 3, gq = t & 7;
        float rh[KS];
        #pragma unroll
        for (int u = 0; u < KS; u++)
            rh[u] = (c < 16) ? rel_h[c*56 + gq*7 + u] : rel_w[(c - 16)*56 + gq*7 + u];
        const float* kbase = g_k + ((long)(b*HP + px)*HP + py)*256 + t;
        for (int i = 0; i < KS; i++) {
            #pragma unroll
            for (int j = 0; j < KS; j++) {
                int m = gq*49 + i*7 + j;
                int off = (i*HP + j)*256;
                float rel = (c < 16) ? rh[i] : rh[j];
                Ks[c*MSK + m] = kbase[off] + rel;
            }
        }
    }
    __syncthreads();

    // S = q^T K with fused exp + row sums (2 passes, low-reg)
    if (ty < 7) sgemm_warp(Ks, qs, mb, ty, tx);
    __syncthreads();

    if (t < 32) {
        float s = 0.f;
        #pragma unroll
        for (int w = 0; w < 7; w++) s += mb[w*32 + t];
        rinv[t] = 1.f / s;
    }
    __syncthreads();

    // collapse heads into transposed layout: Agt[ij*64 + g*8 + g'] =
    //   sum_h E[h*8+g][g'*49+ij] * rinv[h*8+g]
    for (int idx = t; idx < 3136; idx += 256) {
        int ij = idx >> 6;
        int rem = idx & 63;
        int g = rem >> 3, gp = rem & 7;
        int m = gp*49 + ij;
        float s = Ks[g*MSK + m]        * rinv[g]
                + Ks[(8+g)*MSK + m]    * rinv[8+g]
                + Ks[(16+g)*MSK + m]   * rinv[16+g]
                + Ks[(24+g)*MSK + m]   * rinv[24+g];
        Agt[idx] = s;
    }
    __syncthreads();

    // O-GEMM: V straight from gmem (coalesced, consumed once).
    {
        u64 og[8];
        #pragma unroll
        for (int g = 0; g < 8; g++) og[g] = 0ull;
        int c = tx, w = ty;
        const float* vb = gv + ((long)(b*HP + px)*HP + py)*256 + c*8;
        #pragma unroll
        for (int k = 0; k < 7; k++) {
            int ij = k*8 + w;
            if (ij < 49) {
                int i = ij / 7, j = ij - i*7;
                const float4* vp = (const float4*)(vb + (i*HP + j)*256);
                float4 va = vp[0], vbq = vp[1];
                u64 v0 = pk2(va.x, va.y), v1 = pk2(va.z, va.w);
                u64 v2 = pk2(vbq.x, vbq.y), v3 = pk2(vbq.z, vbq.w);
                const float* ab = Agt + ij*64;
                #pragma unroll
                for (int g = 0; g < 8; g++) {
                    ulonglong2 a0 = *(const ulonglong2*)(ab + g*8);
                    ulonglong2 a1 = *(const ulonglong2*)(ab + g*8 + 4);
                    FMA2(og[g], a0.x, v0);
                    FMA2(og[g], a0.y, v1);
                    FMA2(og[g], a1.x, v2);
                    FMA2(og[g], a1.y, v3);
                }
            }
        }
        __syncthreads();   // Agt/E reads done before Rs overwrites Ks
        #pragma unroll
        for (int g = 0; g < 8; g++) {
            float lo, hi; up2(og[g], lo, hi);
            Rs[w*264 + g*33 + c] = lo + hi;
        }
    }
    __syncthreads();

    // final reduce over 8 warps + scrambled store: out[b, g*32+px, py, c]
    {
        int c = tx, g = ty;
        float s = 0.f;
        #pragma unroll
        for (int w = 0; w < 8; w++) s += Rs[w*264 + g*33 + c];
        out[b*262144 + (g*32 + px)*1024 + py*32 + c] = s;
    }
}

// ---------------- launch ----------------
extern "C" void kernel_launch(void* const* d_in, const int* in_sizes, int n_in,
                              void* d_out, int out_size) {
    const float* x   = (const float*)d_in[0];
    const float* wq  = (const float*)d_in[1];
    const float* bq  = (const float*)d_in[2];
    const float* wk  = (const float*)d_in[3];
    const float* bk  = (const float*)d_in[4];
    const float* wv  = (const float*)d_in[5];
    const float* bv  = (const float*)d_in[6];
    const float* rlh = (const float*)d_in[7];
    const float* rlw = (const float*)d_in[8];
    float* out = (float*)d_out;

    cudaFuncSetAttribute(conv_kernel, cudaFuncAttributeMaxDynamicSharedMemorySize, CONV_SMEM);
    cudaFuncSetAttribute(attn_kernel, cudaFuncAttributeMaxDynamicSharedMemorySize, ATTN_SMEM);

    conv_kernel<<<dim3(28, 8, 4), 256, CONV_SMEM>>>(x, wq, bq, wk, bk, wv, bv);

    float* gv_ptr = nullptr;
    cudaGetSymbolAddress((void**)&gv_ptr, g_v);
    attn_kernel<<<NB*NPIX, 256, ATTN_SMEM>>>(rlh, rlw, gv_ptr, out);
}